// round 1
// baseline (speedup 1.0000x reference)
#include <cuda_runtime.h>
#include <math.h>

#define Bn   16
#define Cn   256
#define MIDn 128
#define Hn   128
#define Wn   128
#define HWn  (Hn*Wn)

// ---------------- scratch (static device globals; no allocation) ----------------
__device__ float g_w1t[2304 * 128];              // conv1 weights transposed: [(c*9+k)][o]
__device__ float g_w2t[128 * 256];               // conv2 weights transposed: [c][o]
__device__ float g_h1[(size_t)Bn * MIDn * HWn];  // 134 MB
__device__ float g_xc[(size_t)Bn * Cn * HWn];    // 268 MB
__device__ float g_pooled[Bn * Cn];
__device__ float g_scoreT[(size_t)Bn * Cn * Cn]; // transposed: [b][e][c]

__device__ __forceinline__ float leaky(float v) { return v >= 0.f ? v : 0.2f * v; }

__device__ __forceinline__ void fma2(unsigned long long& d, unsigned long long a,
                                     unsigned long long b) {
    asm("fma.rn.f32x2 %0, %1, %2, %0;" : "+l"(d) : "l"(a), "l"(b));
}

// ---------------- kernel 0: weight transposes ----------------
__global__ void transpose_kernel(const float* __restrict__ w1,
                                 const float* __restrict__ w2) {
    int idx = blockIdx.x * 256 + threadIdx.x;
    if (idx < 128 * 2304) {            // conv1: [o][c*9+k] -> [c*9+k][o]
        int o = idx / 2304, rem = idx - o * 2304;
        g_w1t[rem * 128 + o] = w1[idx];
    }
    if (idx < 256 * 128) {             // conv2: [o][c] -> [c][o]
        int o = idx >> 7, c = idx & 127;
        g_w2t[c * 256 + o] = w2[idx];
    }
}

// ---------------- kernel 1: 3x3 reflect conv (256->128) + leaky ----------------
// Block = one (b, y): all 128 out-channels x all 128 x.  256 threads.
// Per-thread tile 8(o, as 4 f32x2 pairs) x 8(x).  K loop over c (load 3 input rows
// + 9*128 weights to smem per c), inner 9 taps with packed fma.rn.f32x2.
__global__ __launch_bounds__(256, 2) void conv1_kernel(const float* __restrict__ x) {
    __shared__ __align__(16) float sW[9 * 128];
    __shared__ float sX[3][132];
    const int y = blockIdx.x, b = blockIdx.y;
    const int tid = threadIdx.x;
    const int tn = tid & 15;          // pixel lane: x = tn + 16*j
    const int tm = tid >> 4;          // o pair:    o = 32*ii + 2*tm (+q)

    unsigned long long acc[4][8];
#pragma unroll
    for (int ii = 0; ii < 4; ii++)
#pragma unroll
        for (int j = 0; j < 8; j++) acc[ii][j] = 0ULL;

    int r0 = y - 1; if (r0 < 0) r0 = 1;
    int r2 = y + 1; if (r2 > 127) r2 = 126;
    const int rows[3] = {r0, y, r2};
    const float* xb = x + (size_t)b * Cn * HWn;

    for (int c = 0; c < Cn; c++) {
        // input patch: 3 rows x cols [-1..128] (reflect)
        for (int t = tid; t < 3 * 130; t += 256) {
            int dy = t / 130, col = t - dy * 130;
            int cx = col - 1;
            if (cx < 0) cx = 1;
            if (cx > 127) cx = 126;
            sX[dy][col] = xb[((size_t)c * Hn + rows[dy]) * Wn + cx];
        }
        // weights for this c: 9*128, o-contiguous
        const float* wsrc = g_w1t + (size_t)c * 9 * 128;
        for (int t = tid; t < 1152; t += 256) sW[t] = wsrc[t];
        __syncthreads();

        const unsigned long long* sW2 =
            reinterpret_cast<const unsigned long long*>(sW);
#pragma unroll
        for (int ky = 0; ky < 3; ky++) {
#pragma unroll
            for (int kx = 0; kx < 3; kx++) {
                const int k = ky * 3 + kx;
                unsigned long long ap[4];
#pragma unroll
                for (int ii = 0; ii < 4; ii++)
                    ap[ii] = sW2[k * 64 + ii * 16 + tm];   // pair (o, o+1)
#pragma unroll
                for (int j = 0; j < 8; j++) {
                    float xv = sX[ky][tn + 16 * j + kx];
                    unsigned long long xd;
                    asm("mov.b64 %0, {%1, %1};" : "=l"(xd) : "f"(xv));
#pragma unroll
                    for (int ii = 0; ii < 4; ii++) fma2(acc[ii][j], ap[ii], xd);
                }
            }
        }
        __syncthreads();
    }

    float* hb = g_h1 + (size_t)b * MIDn * HWn + (size_t)y * Wn;
#pragma unroll
    for (int ii = 0; ii < 4; ii++) {
        const int o0 = ii * 32 + tm * 2;
#pragma unroll
        for (int j = 0; j < 8; j++) {
            unsigned long long u = acc[ii][j];
            float lo = __uint_as_float((unsigned)u);
            float hi = __uint_as_float((unsigned)(u >> 32));
            int xcol = tn + 16 * j;
            hb[(size_t)o0 * HWn + xcol]       = leaky(lo);
            hb[(size_t)(o0 + 1) * HWn + xcol] = leaky(hi);
        }
    }
}

// ---------------- kernel 2: 1x1 conv (128->256) + leaky ----------------
// GEMM per (b, y, half-of-o): M=128, N=128, K=128.  8x8 register tile.
__global__ __launch_bounds__(256, 2) void conv2_kernel() {
    __shared__ float sA[16][128];
    __shared__ float sB[16][128];
    const int y = blockIdx.x, oh = blockIdx.y, b = blockIdx.z;
    const int tid = threadIdx.x, tn = tid & 15, tm = tid >> 4;
    float acc[8][8] = {};
    const float* h1b = g_h1 + (size_t)b * MIDn * HWn + (size_t)y * Wn;

    for (int kc = 0; kc < 128; kc += 16) {
        for (int t = tid; t < 2048; t += 256) {
            int kk = t >> 7, ml = t & 127;
            sA[kk][ml] = g_w2t[(size_t)(kc + kk) * 256 + oh * 128 + ml];
        }
        for (int t = tid; t < 2048; t += 256) {
            int kk = t >> 7, xx = t & 127;
            sB[kk][xx] = h1b[(size_t)(kc + kk) * HWn + xx];
        }
        __syncthreads();
#pragma unroll
        for (int kk = 0; kk < 16; kk++) {
            float a[8], bb[8];
#pragma unroll
            for (int i = 0; i < 8; i++) a[i] = sA[kk][tm + 16 * i];
#pragma unroll
            for (int j = 0; j < 8; j++) bb[j] = sB[kk][tn + 16 * j];
#pragma unroll
            for (int i = 0; i < 8; i++)
#pragma unroll
                for (int j = 0; j < 8; j++) acc[i][j] += a[i] * bb[j];
        }
        __syncthreads();
    }
    float* xcb = g_xc + ((size_t)b * Cn + oh * 128) * HWn + (size_t)y * Wn;
#pragma unroll
    for (int i = 0; i < 8; i++)
#pragma unroll
        for (int j = 0; j < 8; j++)
            xcb[(size_t)(tm + 16 * i) * HWn + tn + 16 * j] = leaky(acc[i][j]);
}

// ---------------- kernel 3: global average pool ----------------
__global__ void pool_kernel() {
    const int bc = blockIdx.x, tid = threadIdx.x;
    const float* p = g_xc + (size_t)bc * HWn;
    float s = 0.f;
    for (int i = tid; i < HWn; i += 256) s += p[i];
    __shared__ float red[256];
    red[tid] = s;
    __syncthreads();
    for (int st = 128; st; st >>= 1) {
        if (tid < st) red[tid] += red[tid + st];
        __syncthreads();
    }
    if (tid == 0) g_pooled[bc] = red[0] * (1.0f / (float)HWn);
}

// ---------------- kernel 4: MLP + outer-product score + softmax ----------------
// One block per batch.  Stores score TRANSPOSED ([b][e][c]) so the attention
// GEMM's A-tile loads are coalesced.
__global__ void mlp_score_kernel(const float* __restrict__ w1, const float* __restrict__ b1,
                                 const float* __restrict__ w2, const float* __restrict__ b2) {
    const int b = blockIdx.x, tid = threadIdx.x;
    __shared__ float sp[256], sh[64], sm_[256];
    sp[tid] = g_pooled[b * 256 + tid];
    __syncthreads();
    if (tid < 64) {
        float s = b1[tid];
        for (int c = 0; c < 256; c++) s += sp[c] * w1[tid * 256 + c];
        sh[tid] = leaky(s);
    }
    __syncthreads();
    {
        float s = b2[tid];
        for (int j = 0; j < 64; j++) s += sh[j] * w2[tid * 64 + j];
        sm_[tid] = s;
    }
    __syncthreads();
    const int lane = tid & 31, w = tid >> 5;  // warp per row group
    for (int r = w; r < 256; r += 8) {
        float mr = sm_[r];
        float mx = -1e30f;
        for (int e = lane; e < 256; e += 32) mx = fmaxf(mx, mr * sm_[e]);
        for (int off = 16; off; off >>= 1) mx = fmaxf(mx, __shfl_xor_sync(~0u, mx, off));
        float sum = 0.f;
        for (int e = lane; e < 256; e += 32) sum += expf(mr * sm_[e] - mx);
        for (int off = 16; off; off >>= 1) sum += __shfl_xor_sync(~0u, sum, off);
        float inv = 1.0f / sum;
        for (int e = lane; e < 256; e += 32)
            g_scoreT[((size_t)b * 256 + e) * 256 + r] = expf(mr * sm_[e] - mx) * inv;
    }
}

// ---------------- kernel 5: attention GEMM + residual ----------------
// out[b,m,p] = xc[b,m,p] + sum_e score[b,m,e] * xc[b,e,p].  M=128/blk, N=128, K=256.
__global__ __launch_bounds__(256, 2) void attn_kernel(float* __restrict__ out) {
    __shared__ float sA[16][128];
    __shared__ float sB[16][128];
    const int y = blockIdx.x, oh = blockIdx.y, b = blockIdx.z;
    const int tid = threadIdx.x, tn = tid & 15, tm = tid >> 4;
    float acc[8][8] = {};
    const float* xcb = g_xc + (size_t)b * Cn * HWn + (size_t)y * Wn;

    for (int kc = 0; kc < 256; kc += 16) {
        for (int t = tid; t < 2048; t += 256) {
            int kk = t >> 7, ml = t & 127;
            sA[kk][ml] = g_scoreT[((size_t)b * 256 + kc + kk) * 256 + oh * 128 + ml];
        }
        for (int t = tid; t < 2048; t += 256) {
            int kk = t >> 7, xx = t & 127;
            sB[kk][xx] = xcb[(size_t)(kc + kk) * HWn + xx];
        }
        __syncthreads();
#pragma unroll
        for (int kk = 0; kk < 16; kk++) {
            float a[8], bb[8];
#pragma unroll
            for (int i = 0; i < 8; i++) a[i] = sA[kk][tm + 16 * i];
#pragma unroll
            for (int j = 0; j < 8; j++) bb[j] = sB[kk][tn + 16 * j];
#pragma unroll
            for (int i = 0; i < 8; i++)
#pragma unroll
                for (int j = 0; j < 8; j++) acc[i][j] += a[i] * bb[j];
        }
        __syncthreads();
    }
    const float* resb = g_xc + ((size_t)b * Cn + oh * 128) * HWn + (size_t)y * Wn;
    float* ob = out + ((size_t)b * Cn + oh * 128) * HWn + (size_t)y * Wn;
#pragma unroll
    for (int i = 0; i < 8; i++)
#pragma unroll
        for (int j = 0; j < 8; j++) {
            size_t off = (size_t)(tm + 16 * i) * HWn + tn + 16 * j;
            ob[off] = acc[i][j] + resb[off];
        }
}

// ---------------- launcher ----------------
extern "C" void kernel_launch(void* const* d_in, const int* in_sizes, int n_in,
                              void* d_out, int out_size) {
    const float* x    = (const float*)d_in[0];
    const float* c1w  = (const float*)d_in[1];
    const float* c2w  = (const float*)d_in[2];
    const float* mw1  = (const float*)d_in[3];
    const float* mb1  = (const float*)d_in[4];
    const float* mw2  = (const float*)d_in[5];
    const float* mb2  = (const float*)d_in[6];
    float* out = (float*)d_out;

    transpose_kernel<<<1280, 256>>>(c1w, c2w);
    conv1_kernel<<<dim3(Hn, Bn), 256>>>(x);
    conv2_kernel<<<dim3(Hn, 2, Bn), 256>>>();
    pool_kernel<<<Bn * Cn, 256>>>();
    mlp_score_kernel<<<Bn, 256>>>(mw1, mb1, mw2, mb2);
    attn_kernel<<<dim3(Hn, 2, Bn), 256>>>(out);
}

// round 3
// speedup vs baseline: 1.4743x; 1.4743x over previous
#include <cuda_runtime.h>
#include <cuda_bf16.h>
#include <cstdint>
#include <math.h>

#define Bn   16
#define Cn   256
#define MIDn 128
#define Hn   128
#define Wn   128
#define HWn  (Hn*Wn)
#define ST   72        // padded smem row stride (elems) for ldmatrix tiles

// ================= warp-MMA helpers (portable sm_80+ path) =================
__device__ __forceinline__ uint32_t smem_u32(const void* p) {
    uint32_t a;
    asm("{ .reg .u64 t; cvta.to.shared.u64 t, %1; cvt.u32.u64 %0, t; }" : "=r"(a) : "l"(p));
    return a;
}
__device__ __forceinline__ void ldsm_x4(uint32_t* r, uint32_t addr) {
    asm volatile("ldmatrix.sync.aligned.m8n8.x4.shared.b16 {%0,%1,%2,%3}, [%4];"
                 : "=r"(r[0]), "=r"(r[1]), "=r"(r[2]), "=r"(r[3]) : "r"(addr));
}
__device__ __forceinline__ void mma_bf16(float* d, const uint32_t* a, uint32_t b0, uint32_t b1) {
    asm volatile("mma.sync.aligned.m16n8k16.row.col.f32.bf16.bf16.f32 "
                 "{%0,%1,%2,%3}, {%4,%5,%6,%7}, {%8,%9}, {%0,%1,%2,%3};"
                 : "+f"(d[0]), "+f"(d[1]), "+f"(d[2]), "+f"(d[3])
                 : "r"(a[0]), "r"(a[1]), "r"(a[2]), "r"(a[3]), "r"(b0), "r"(b1));
}
__device__ __forceinline__ float leaky(float v) { return v >= 0.f ? v : 0.2f * v; }

// ================= scratch =================
__device__ __nv_bfloat16 g_w1h[4 * 9 * 128 * 64];   // [chunk][tap][o][c]
__device__ __nv_bfloat16 g_w1l[4 * 9 * 128 * 64];
__device__ __nv_bfloat16 g_w2h[256 * 128];          // [o][c]
__device__ __nv_bfloat16 g_w2l[256 * 128];
__device__ float g_h1[(size_t)Bn * MIDn * HWn];
__device__ float g_xc[(size_t)Bn * Cn * HWn];
__device__ float g_pooled[Bn * Cn];
__device__ __nv_bfloat16 g_scoreH[(size_t)Bn * Cn * Cn];  // [b][m][e]
__device__ __nv_bfloat16 g_scoreL[(size_t)Bn * Cn * Cn];

// ---------------- kernel 0: weight prep (bf16 split) ----------------
__global__ void prep_kernel(const float* __restrict__ w1, const float* __restrict__ w2) {
    int idx = blockIdx.x * 256 + threadIdx.x;
    if (idx < 128 * 256 * 9) {          // w1: [o][c][tap]
        int o = idx / 2304, rem = idx - o * 2304;
        int c = rem / 9, tap = rem - c * 9;
        float w = w1[idx];
        __nv_bfloat16 h = __float2bfloat16(w);
        __nv_bfloat16 l = __float2bfloat16(w - __bfloat162float(h));
        int chunk = c >> 6, cc = c & 63;
        int off = (((chunk * 9 + tap) << 7) + o) * 64 + cc;
        g_w1h[off] = h;
        g_w1l[off] = l;
    }
    if (idx < 256 * 128) {              // w2 split, natural [o][c]
        float w = w2[idx];
        __nv_bfloat16 h = __float2bfloat16(w);
        g_w2h[idx] = h;
        g_w2l[idx] = __float2bfloat16(w - __bfloat162float(h));
    }
}

// ---------------- kernel 1: 3x3 reflect conv (256->128) + leaky, HMMA ----------------
// Block (y, b): M=128 o, N=128 x.  K = 4 chunks x 9 taps x 64 c.
#define C1_AH 0
#define C1_AL 18432
#define C1_BH 36864
#define C1_BL 55296
#define C1_XS 73728
#define C1_SMEM (C1_XS + 64 * 3 * 133 * 4)   // 175872

__global__ __launch_bounds__(256) void conv1_tc(const float* __restrict__ x) {
    extern __shared__ char sm[];
    const uint32_t sb = smem_u32(sm);
    float* XS = (float*)(sm + C1_XS);
    __nv_bfloat16* sAh = (__nv_bfloat16*)(sm + C1_AH);
    __nv_bfloat16* sAl = (__nv_bfloat16*)(sm + C1_AL);
    __nv_bfloat16* sBh = (__nv_bfloat16*)(sm + C1_BH);
    __nv_bfloat16* sBl = (__nv_bfloat16*)(sm + C1_BL);

    const int tid = threadIdx.x, lane = tid & 31, wid = tid >> 5;
    const int y = blockIdx.x, b = blockIdx.y;
    const int m0 = (wid & 3) * 32, n0 = (wid >> 2) * 64;

    // per-lane ldmatrix address offsets (bytes, within a tile)
    const uint32_t aoff = ((m0 + (lane & 15)) * ST + (lane >> 4) * 8) * 2;
    const uint32_t boff = ((n0 + (lane & 7) + ((lane >> 3) & 1) * 8) * ST + (lane >> 4) * 8) * 2;

    float acc[2][8][4];
#pragma unroll
    for (int mi = 0; mi < 2; mi++)
#pragma unroll
        for (int f = 0; f < 8; f++)
#pragma unroll
            for (int q = 0; q < 4; q++) acc[mi][f][q] = 0.f;

    int r0 = y - 1; if (r0 < 0) r0 = 1;
    int r2 = y + 1; if (r2 > 127) r2 = 126;
    const int rows[3] = {r0, y, r2};
    const float* xb = x + (size_t)b * Cn * HWn;

    for (int chunk = 0; chunk < 4; chunk++) {
        // stage fp32 neighborhood [64c][3 rows][130 cols] (pad 133) with reflect
        for (int idx = tid; idx < 64 * 390; idx += 256) {
            int cc = idx / 390, r = idx - cc * 390;
            int ky = r / 130, col = r - ky * 130;
            int cx = col - 1;
            if (cx < 0) cx = 1;
            if (cx > 127) cx = 126;
            XS[(cc * 3 + ky) * 133 + col] =
                xb[(size_t)(chunk * 64 + cc) * HWn + (size_t)rows[ky] * Wn + cx];
        }
        __syncthreads();

        for (int tap = 0; tap < 9; tap++) {
            const int ky = tap / 3, kx = tap - ky * 3;
            // A tiles: copy 128x64 bf16 hi/lo (uint4)
            {
                const uint4* srcH = (const uint4*)(g_w1h + ((chunk * 9 + tap) << 13));
                const uint4* srcL = (const uint4*)(g_w1l + ((chunk * 9 + tap) << 13));
                for (int i = tid; i < 1024; i += 256) {
                    int row = i >> 3, q = i & 7;
                    *(uint4*)(sAh + row * ST + q * 8) = srcH[i];
                    *(uint4*)(sAl + row * ST + q * 8) = srcL[i];
                }
            }
            // B tiles [n=128 pix][k=64 c] hi/lo from XS
            for (int i = tid; i < 8192; i += 256) {
                int n = i >> 6, cc = i & 63;
                float v = XS[(cc * 3 + ky) * 133 + n + kx];
                __nv_bfloat16 h = __float2bfloat16(v);
                sBh[n * ST + cc] = h;
                sBl[n * ST + cc] = __float2bfloat16(v - __bfloat162float(h));
            }
            __syncthreads();

            // 4 k16-steps, 48 HMMA each per warp
#pragma unroll
            for (int ks = 0; ks < 4; ks++) {
                const uint32_t kb = ks * 32;
                uint32_t ah[8], al[8], bh[16], bl[16];
                ldsm_x4(ah,     sb + C1_AH + aoff + kb);
                ldsm_x4(ah + 4, sb + C1_AH + aoff + 16 * ST * 2 + kb);
                ldsm_x4(al,     sb + C1_AL + aoff + kb);
                ldsm_x4(al + 4, sb + C1_AL + aoff + 16 * ST * 2 + kb);
#pragma unroll
                for (int f = 0; f < 4; f++) {
                    ldsm_x4(bh + 4 * f, sb + C1_BH + boff + f * 16 * ST * 2 + kb);
                    ldsm_x4(bl + 4 * f, sb + C1_BL + boff + f * 16 * ST * 2 + kb);
                }
#pragma unroll
                for (int mi = 0; mi < 2; mi++) {
                    const uint32_t* Ah = ah + 4 * mi;
                    const uint32_t* Al = al + 4 * mi;
#pragma unroll
                    for (int f = 0; f < 4; f++) {
                        mma_bf16(acc[mi][2 * f],     Ah, bh[4 * f],     bh[4 * f + 2]);
                        mma_bf16(acc[mi][2 * f],     Ah, bl[4 * f],     bl[4 * f + 2]);
                        mma_bf16(acc[mi][2 * f],     Al, bh[4 * f],     bh[4 * f + 2]);
                        mma_bf16(acc[mi][2 * f + 1], Ah, bh[4 * f + 1], bh[4 * f + 3]);
                        mma_bf16(acc[mi][2 * f + 1], Ah, bl[4 * f + 1], bl[4 * f + 3]);
                        mma_bf16(acc[mi][2 * f + 1], Al, bh[4 * f + 1], bh[4 * f + 3]);
                    }
                }
            }
            __syncthreads();
        }
    }

    // epilogue: leaky -> g_h1
    float* hb = g_h1 + (size_t)b * MIDn * HWn + (size_t)y * Wn;
    const int dr = lane >> 2, dc = (lane & 3) * 2;
#pragma unroll
    for (int mi = 0; mi < 2; mi++)
#pragma unroll
        for (int f = 0; f < 8; f++) {
            int o = m0 + mi * 16 + dr, pix = n0 + f * 8 + dc;
            float2 v0 = {leaky(acc[mi][f][0]), leaky(acc[mi][f][1])};
            float2 v1 = {leaky(acc[mi][f][2]), leaky(acc[mi][f][3])};
            *(float2*)&hb[(size_t)o * HWn + pix] = v0;
            *(float2*)&hb[(size_t)(o + 8) * HWn + pix] = v1;
        }
}

// ---------------- generic tiles for conv2 / attn ----------------
#define G_AH 0
#define G_AL 18432
#define G_BH 36864
#define G_BL 55296
#define G_SMEM 73728

// conv2: out[b, o, y, :] GEMM M=128(o half) x N=128(x) x K=128, + leaky
__global__ __launch_bounds__(256) void conv2_tc() {
    extern __shared__ char sm[];
    const uint32_t sb = smem_u32(sm);
    __nv_bfloat16* sAh = (__nv_bfloat16*)(sm + G_AH);
    __nv_bfloat16* sAl = (__nv_bfloat16*)(sm + G_AL);
    __nv_bfloat16* sBh = (__nv_bfloat16*)(sm + G_BH);
    __nv_bfloat16* sBl = (__nv_bfloat16*)(sm + G_BL);

    const int tid = threadIdx.x, lane = tid & 31, wid = tid >> 5;
    const int y = blockIdx.x, mh = blockIdx.y, b = blockIdx.z;
    const int m0 = (wid & 3) * 32, n0 = (wid >> 2) * 64;
    const uint32_t aoff = ((m0 + (lane & 15)) * ST + (lane >> 4) * 8) * 2;
    const uint32_t boff = ((n0 + (lane & 7) + ((lane >> 3) & 1) * 8) * ST + (lane >> 4) * 8) * 2;

    float acc[2][8][4];
#pragma unroll
    for (int mi = 0; mi < 2; mi++)
#pragma unroll
        for (int f = 0; f < 8; f++)
#pragma unroll
            for (int q = 0; q < 4; q++) acc[mi][f][q] = 0.f;

    const float* h1b = g_h1 + (size_t)b * MIDn * HWn + (size_t)y * Wn;

    for (int kc = 0; kc < 128; kc += 64) {
        for (int i = tid; i < 1024; i += 256) {
            int row = i >> 3, q = i & 7;
            *(uint4*)(sAh + row * ST + q * 8) =
                ((const uint4*)(g_w2h + (size_t)(mh * 128 + row) * 128 + kc))[q];
            *(uint4*)(sAl + row * ST + q * 8) =
                ((const uint4*)(g_w2l + (size_t)(mh * 128 + row) * 128 + kc))[q];
        }
        for (int i = tid; i < 8192; i += 256) {
            int n = i & 127, k = i >> 7;
            float v = h1b[(size_t)(kc + k) * HWn + n];
            __nv_bfloat16 h = __float2bfloat16(v);
            sBh[n * ST + k] = h;
            sBl[n * ST + k] = __float2bfloat16(v - __bfloat162float(h));
        }
        __syncthreads();
#pragma unroll
        for (int ks = 0; ks < 4; ks++) {
            const uint32_t kb = ks * 32;
            uint32_t ah[8], al[8], bh[16], bl[16];
            ldsm_x4(ah,     sb + G_AH + aoff + kb);
            ldsm_x4(ah + 4, sb + G_AH + aoff + 16 * ST * 2 + kb);
            ldsm_x4(al,     sb + G_AL + aoff + kb);
            ldsm_x4(al + 4, sb + G_AL + aoff + 16 * ST * 2 + kb);
#pragma unroll
            for (int f = 0; f < 4; f++) {
                ldsm_x4(bh + 4 * f, sb + G_BH + boff + f * 16 * ST * 2 + kb);
                ldsm_x4(bl + 4 * f, sb + G_BL + boff + f * 16 * ST * 2 + kb);
            }
#pragma unroll
            for (int mi = 0; mi < 2; mi++) {
                const uint32_t* Ah = ah + 4 * mi;
                const uint32_t* Al = al + 4 * mi;
#pragma unroll
                for (int f = 0; f < 4; f++) {
                    mma_bf16(acc[mi][2 * f],     Ah, bh[4 * f],     bh[4 * f + 2]);
                    mma_bf16(acc[mi][2 * f],     Ah, bl[4 * f],     bl[4 * f + 2]);
                    mma_bf16(acc[mi][2 * f],     Al, bh[4 * f],     bh[4 * f + 2]);
                    mma_bf16(acc[mi][2 * f + 1], Ah, bh[4 * f + 1], bh[4 * f + 3]);
                    mma_bf16(acc[mi][2 * f + 1], Ah, bl[4 * f + 1], bl[4 * f + 3]);
                    mma_bf16(acc[mi][2 * f + 1], Al, bh[4 * f + 1], bh[4 * f + 3]);
                }
            }
        }
        __syncthreads();
    }

    float* xcb = g_xc + ((size_t)b * Cn + mh * 128) * HWn + (size_t)y * Wn;
    const int dr = lane >> 2, dc = (lane & 3) * 2;
#pragma unroll
    for (int mi = 0; mi < 2; mi++)
#pragma unroll
        for (int f = 0; f < 8; f++) {
            int o = m0 + mi * 16 + dr, pix = n0 + f * 8 + dc;
            float2 v0 = {leaky(acc[mi][f][0]), leaky(acc[mi][f][1])};
            float2 v1 = {leaky(acc[mi][f][2]), leaky(acc[mi][f][3])};
            *(float2*)&xcb[(size_t)o * HWn + pix] = v0;
            *(float2*)&xcb[(size_t)(o + 8) * HWn + pix] = v1;
        }
}

// ---------------- kernel 3: global average pool ----------------
__global__ void pool_kernel() {
    const int bc = blockIdx.x, tid = threadIdx.x;
    const float* p = g_xc + (size_t)bc * HWn;
    float s = 0.f;
    for (int i = tid; i < HWn; i += 256) s += p[i];
    __shared__ float red[256];
    red[tid] = s;
    __syncthreads();
    for (int st = 128; st; st >>= 1) {
        if (tid < st) red[tid] += red[tid + st];
        __syncthreads();
    }
    if (tid == 0) g_pooled[bc] = red[0] * (1.0f / (float)HWn);
}

// ---------------- kernel 4: MLP + outer score + softmax (bf16 split out) ----------------
__global__ void mlp_score_kernel(const float* __restrict__ w1, const float* __restrict__ b1,
                                 const float* __restrict__ w2, const float* __restrict__ b2) {
    const int b = blockIdx.x, tid = threadIdx.x;
    __shared__ float sp[256], sh[64], sm_[256];
    sp[tid] = g_pooled[b * 256 + tid];
    __syncthreads();
    if (tid < 64) {
        float s = b1[tid];
        for (int c = 0; c < 256; c++) s += sp[c] * w1[tid * 256 + c];
        sh[tid] = leaky(s);
    }
    __syncthreads();
    {
        float s = b2[tid];
        for (int j = 0; j < 64; j++) s += sh[j] * w2[tid * 64 + j];
        sm_[tid] = s;
    }
    __syncthreads();
    const int lane = tid & 31, w = tid >> 5;
    for (int r = w; r < 256; r += 8) {
        float mr = sm_[r];
        float mx = -1e30f;
        for (int e = lane; e < 256; e += 32) mx = fmaxf(mx, mr * sm_[e]);
        for (int off = 16; off; off >>= 1) mx = fmaxf(mx, __shfl_xor_sync(~0u, mx, off));
        float sum = 0.f;
        for (int e = lane; e < 256; e += 32) sum += expf(mr * sm_[e] - mx);
        for (int off = 16; off; off >>= 1) sum += __shfl_xor_sync(~0u, sum, off);
        float inv = 1.0f / sum;
        for (int e = lane; e < 256; e += 32) {
            float s = expf(mr * sm_[e] - mx) * inv;
            __nv_bfloat16 h = __float2bfloat16(s);
            size_t off2 = ((size_t)b * 256 + r) * 256 + e;
            g_scoreH[off2] = h;
            g_scoreL[off2] = __float2bfloat16(s - __bfloat162float(h));
        }
    }
}

// ---------------- kernel 5: attention GEMM + residual, HMMA ----------------
__global__ __launch_bounds__(256) void attn_tc(float* __restrict__ out) {
    extern __shared__ char sm[];
    const uint32_t sb = smem_u32(sm);
    __nv_bfloat16* sAh = (__nv_bfloat16*)(sm + G_AH);
    __nv_bfloat16* sAl = (__nv_bfloat16*)(sm + G_AL);
    __nv_bfloat16* sBh = (__nv_bfloat16*)(sm + G_BH);
    __nv_bfloat16* sBl = (__nv_bfloat16*)(sm + G_BL);

    const int tid = threadIdx.x, lane = tid & 31, wid = tid >> 5;
    const int y = blockIdx.x, mh = blockIdx.y, b = blockIdx.z;
    const int m0 = (wid & 3) * 32, n0 = (wid >> 2) * 64;
    const uint32_t aoff = ((m0 + (lane & 15)) * ST + (lane >> 4) * 8) * 2;
    const uint32_t boff = ((n0 + (lane & 7) + ((lane >> 3) & 1) * 8) * ST + (lane >> 4) * 8) * 2;

    float acc[2][8][4];
#pragma unroll
    for (int mi = 0; mi < 2; mi++)
#pragma unroll
        for (int f = 0; f < 8; f++)
#pragma unroll
            for (int q = 0; q < 4; q++) acc[mi][f][q] = 0.f;

    const float* xcb0 = g_xc + (size_t)b * Cn * HWn + (size_t)y * Wn;

    for (int kc = 0; kc < 256; kc += 64) {
        for (int i = tid; i < 1024; i += 256) {
            int row = i >> 3, q = i & 7;
            *(uint4*)(sAh + row * ST + q * 8) =
                ((const uint4*)(g_scoreH + ((size_t)b * 256 + mh * 128 + row) * 256 + kc))[q];
            *(uint4*)(sAl + row * ST + q * 8) =
                ((const uint4*)(g_scoreL + ((size_t)b * 256 + mh * 128 + row) * 256 + kc))[q];
        }
        for (int i = tid; i < 8192; i += 256) {
            int n = i & 127, k = i >> 7;
            float v = xcb0[(size_t)(kc + k) * HWn + n];
            __nv_bfloat16 h = __float2bfloat16(v);
            sBh[n * ST + k] = h;
            sBl[n * ST + k] = __float2bfloat16(v - __bfloat162float(h));
        }
        __syncthreads();
#pragma unroll
        for (int ks = 0; ks < 4; ks++) {
            const uint32_t kb = ks * 32;
            uint32_t ah[8], al[8], bh[16], bl[16];
            ldsm_x4(ah,     sb + G_AH + aoff + kb);
            ldsm_x4(ah + 4, sb + G_AH + aoff + 16 * ST * 2 + kb);
            ldsm_x4(al,     sb + G_AL + aoff + kb);
            ldsm_x4(al + 4, sb + G_AL + aoff + 16 * ST * 2 + kb);
#pragma unroll
            for (int f = 0; f < 4; f++) {
                ldsm_x4(bh + 4 * f, sb + G_BH + boff + f * 16 * ST * 2 + kb);
                ldsm_x4(bl + 4 * f, sb + G_BL + boff + f * 16 * ST * 2 + kb);
            }
#pragma unroll
            for (int mi = 0; mi < 2; mi++) {
                const uint32_t* Ah = ah + 4 * mi;
                const uint32_t* Al = al + 4 * mi;
#pragma unroll
                for (int f = 0; f < 4; f++) {
                    mma_bf16(acc[mi][2 * f],     Ah, bh[4 * f],     bh[4 * f + 2]);
                    mma_bf16(acc[mi][2 * f],     Ah, bl[4 * f],     bl[4 * f + 2]);
                    mma_bf16(acc[mi][2 * f],     Al, bh[4 * f],     bh[4 * f + 2]);
                    mma_bf16(acc[mi][2 * f + 1], Ah, bh[4 * f + 1], bh[4 * f + 3]);
                    mma_bf16(acc[mi][2 * f + 1], Ah, bl[4 * f + 1], bl[4 * f + 3]);
                    mma_bf16(acc[mi][2 * f + 1], Al, bh[4 * f + 1], bh[4 * f + 3]);
                }
            }
        }
        __syncthreads();
    }

    const float* resb = g_xc + ((size_t)b * Cn + mh * 128) * HWn + (size_t)y * Wn;
    float* ob = out + ((size_t)b * Cn + mh * 128) * HWn + (size_t)y * Wn;
    const int dr = lane >> 2, dc = (lane & 3) * 2;
#pragma unroll
    for (int mi = 0; mi < 2; mi++)
#pragma unroll
        for (int f = 0; f < 8; f++) {
            int o = m0 + mi * 16 + dr, pix = n0 + f * 8 + dc;
            size_t o1 = (size_t)o * HWn + pix, o2 = (size_t)(o + 8) * HWn + pix;
            float2 r1 = *(const float2*)&resb[o1];
            float2 r2 = *(const float2*)&resb[o2];
            float2 v1 = {acc[mi][f][0] + r1.x, acc[mi][f][1] + r1.y};
            float2 v2 = {acc[mi][f][2] + r2.x, acc[mi][f][3] + r2.y};
            *(float2*)&ob[o1] = v1;
            *(float2*)&ob[o2] = v2;
        }
}

// ---------------- launcher ----------------
extern "C" void kernel_launch(void* const* d_in, const int* in_sizes, int n_in,
                              void* d_out, int out_size) {
    const float* x   = (const float*)d_in[0];
    const float* c1w = (const float*)d_in[1];
    const float* c2w = (const float*)d_in[2];
    const float* mw1 = (const float*)d_in[3];
    const float* mb1 = (const float*)d_in[4];
    const float* mw2 = (const float*)d_in[5];
    const float* mb2 = (const float*)d_in[6];
    float* out = (float*)d_out;

    cudaFuncSetAttribute(conv1_tc, cudaFuncAttributeMaxDynamicSharedMemorySize, C1_SMEM);
    cudaFuncSetAttribute(conv2_tc, cudaFuncAttributeMaxDynamicSharedMemorySize, G_SMEM);
    cudaFuncSetAttribute(attn_tc,  cudaFuncAttributeMaxDynamicSharedMemorySize, G_SMEM);

    prep_kernel<<<1152, 256>>>(c1w, c2w);
    conv1_tc<<<dim3(Hn, Bn), 256, C1_SMEM>>>(x);
    conv2_tc<<<dim3(Hn, 2, Bn), 256, G_SMEM>>>();
    pool_kernel<<<Bn * Cn, 256>>>();
    mlp_score_kernel<<<Bn, 256>>>(mw1, mb1, mw2, mb2);
    attn_tc<<<dim3(Hn, 2, Bn), 256, G_SMEM>>>(out);
}

// round 4
// speedup vs baseline: 1.9806x; 1.3434x over previous
#include <cuda_runtime.h>
#include <cuda_bf16.h>
#include <cstdint>
#include <math.h>

#define Bn   16
#define Cn   256
#define MIDn 128
#define Hn   128
#define Wn   128
#define HWn  (Hn*Wn)
#define ST   72        // padded smem row stride (elems) for ldmatrix tiles

// ================= warp-MMA helpers =================
__device__ __forceinline__ uint32_t smem_u32(const void* p) {
    uint32_t a;
    asm("{ .reg .u64 t; cvta.to.shared.u64 t, %1; cvt.u32.u64 %0, t; }" : "=r"(a) : "l"(p));
    return a;
}
__device__ __forceinline__ void ldsm_x4(uint32_t* r, uint32_t addr) {
    asm volatile("ldmatrix.sync.aligned.m8n8.x4.shared.b16 {%0,%1,%2,%3}, [%4];"
                 : "=r"(r[0]), "=r"(r[1]), "=r"(r[2]), "=r"(r[3]) : "r"(addr));
}
__device__ __forceinline__ void mma_bf16(float* d, const uint32_t* a, uint32_t b0, uint32_t b1) {
    asm volatile("mma.sync.aligned.m16n8k16.row.col.f32.bf16.bf16.f32 "
                 "{%0,%1,%2,%3}, {%4,%5,%6,%7}, {%8,%9}, {%0,%1,%2,%3};"
                 : "+f"(d[0]), "+f"(d[1]), "+f"(d[2]), "+f"(d[3])
                 : "r"(a[0]), "r"(a[1]), "r"(a[2]), "r"(a[3]), "r"(b0), "r"(b1));
}
__device__ __forceinline__ void cp16(uint32_t saddr, const void* g) {
    asm volatile("cp.async.cg.shared.global [%0], [%1], 16;" :: "r"(saddr), "l"(g) : "memory");
}
#define CP_COMMIT() asm volatile("cp.async.commit_group;" ::: "memory")
#define CP_WAIT0()  asm volatile("cp.async.wait_group 0;" ::: "memory")
__device__ __forceinline__ float leaky(float v) { return v >= 0.f ? v : 0.2f * v; }
__device__ __forceinline__ uint32_t pack_hi(float a, float b) {
    __nv_bfloat16 h0 = __float2bfloat16(a), h1 = __float2bfloat16(b);
    return (uint32_t)__bfloat16_as_ushort(h0) | ((uint32_t)__bfloat16_as_ushort(h1) << 16);
}
__device__ __forceinline__ uint32_t pack_lo(float a, float b) {
    __nv_bfloat16 h0 = __float2bfloat16(a), h1 = __float2bfloat16(b);
    __nv_bfloat16 l0 = __float2bfloat16(a - __bfloat162float(h0));
    __nv_bfloat16 l1 = __float2bfloat16(b - __bfloat162float(h1));
    return (uint32_t)__bfloat16_as_ushort(l0) | ((uint32_t)__bfloat16_as_ushort(l1) << 16);
}

// ================= scratch =================
__device__ __nv_bfloat16 g_w1h[4 * 9 * 128 * 64];   // [chunk*9+tap][o][cc]
__device__ __nv_bfloat16 g_w1l[4 * 9 * 128 * 64];
__device__ __nv_bfloat16 g_w2h[256 * 128];          // [o][mid]
__device__ __nv_bfloat16 g_w2l[256 * 128];
__device__ __nv_bfloat16 g_h1h[(size_t)Bn * HWn * MIDn];   // [b][y][pix][mid]
__device__ __nv_bfloat16 g_h1l[(size_t)Bn * HWn * MIDn];
__device__ __nv_bfloat16 g_xch[(size_t)Bn * HWn * Cn];     // [b][y][pix][c]
__device__ __nv_bfloat16 g_xcl[(size_t)Bn * HWn * Cn];
__device__ float g_xc32[(size_t)Bn * HWn * Cn];            // [b][y][pix][c]
__device__ float g_ppart[Bn * 64 * Cn];
__device__ float g_pooled[Bn * Cn];
__device__ __nv_bfloat16 g_scoreH[(size_t)Bn * Cn * Cn];   // [b][m(c)][e]
__device__ __nv_bfloat16 g_scoreL[(size_t)Bn * Cn * Cn];

// ---------------- kernel 0: weight prep (bf16 split) ----------------
__global__ void prep_kernel(const float* __restrict__ w1, const float* __restrict__ w2) {
    int idx = blockIdx.x * 256 + threadIdx.x;
    if (idx < 128 * 256 * 9) {          // w1 in: [o][c][tap]
        int o = idx / 2304, rem = idx - o * 2304;
        int c = rem / 9, tap = rem - c * 9;
        float w = w1[idx];
        __nv_bfloat16 h = __float2bfloat16(w);
        __nv_bfloat16 l = __float2bfloat16(w - __bfloat162float(h));
        int chunk = c >> 6, cc = c & 63;
        int off = (((chunk * 9 + tap) << 7) + o) * 64 + cc;
        g_w1h[off] = h;
        g_w1l[off] = l;
    }
    if (idx < 256 * 128) {              // w2 natural [o][mid]
        float w = w2[idx];
        __nv_bfloat16 h = __float2bfloat16(w);
        g_w2h[idx] = h;
        g_w2l[idx] = __float2bfloat16(w - __bfloat162float(h));
    }
}

// ---------------- kernel 1: 3x3 reflect conv (256->128) + leaky, HMMA ----------------
// Block (y,b): M = 128 pixels, N = 128 out-ch, K = 4 chunks x 9 taps x 64.
// A = input window hi/lo (split once per chunk, shared by all 9 taps via row shift).
// B = weights hi/lo, cp.async double-buffered per tap.
#define C1_XWH    0
#define C1_PLANE  (132 * ST)                 // elems per ky plane = 9504
#define C1_PLANEB (C1_PLANE * 2)             // 19008 bytes
#define C1_XWL    57088
#define C1_WBUF0  114176
#define C1_WHALF  18432                      // bytes per hi (or lo) weight tile
#define C1_WBUFSZ 36864
#define C1_SMEM   (C1_WBUF0 + 2 * C1_WBUFSZ) // 187,904

__global__ __launch_bounds__(256) void conv1_tc(const float* __restrict__ x) {
    extern __shared__ char sm[];
    const uint32_t sb = smem_u32(sm);
    const int tid = threadIdx.x, lane = tid & 31, wid = tid >> 5;
    const int y = blockIdx.x, b = blockIdx.y;
    const int m0 = (wid & 3) * 32, n0 = (wid >> 2) * 64;

    const uint32_t boff = ((n0 + (lane & 7) + ((lane >> 3) & 1) * 8) * ST + (lane >> 4) * 8) * 2;
    const int arow = m0 + (lane & 15);
    const int acol = (lane >> 4) * 8;

    float acc[2][8][4];
#pragma unroll
    for (int mi = 0; mi < 2; mi++)
#pragma unroll
        for (int f = 0; f < 8; f++)
#pragma unroll
            for (int q = 0; q < 4; q++) acc[mi][f][q] = 0.f;

    int r0 = y - 1; if (r0 < 0) r0 = 1;
    int r2 = y + 1; if (r2 > 127) r2 = 126;
    const int rows[3] = {r0, y, r2};
    const float* xb = x + (size_t)b * Cn * HWn;
    __nv_bfloat16* XWh = (__nv_bfloat16*)(sm + C1_XWH);
    __nv_bfloat16* XWl = (__nv_bfloat16*)(sm + C1_XWL);

    // weight prefetch helper
    auto cpW = [&](int gidx, int buf) {
        uint32_t dst = sb + C1_WBUF0 + buf * C1_WBUFSZ;
        const uint4* srcH = (const uint4*)(g_w1h + ((size_t)gidx << 13));
        const uint4* srcL = (const uint4*)(g_w1l + ((size_t)gidx << 13));
        for (int i = tid; i < 1024; i += 256) {
            int row = i >> 3, q = i & 7;
            uint32_t so = (uint32_t)(row * ST + q * 8) * 2;
            cp16(dst + so, srcH + i);
            cp16(dst + C1_WHALF + so, srcL + i);
        }
        CP_COMMIT();
    };
    cpW(0, 0);

    for (int t = 0; t < 36; t++) {
        const int chunk = t / 9, tap = t - chunk * 9;
        const int ky = tap / 3, kx = tap - ky * 3;
        if (tap == 0) {
            __syncthreads();   // prev chunk's MMA done before XW overwrite
            for (int idx = tid; idx < 64 * 390; idx += 256) {
                int cc = idx / 390, r = idx - cc * 390;
                int kyb = r / 130, col = r - kyb * 130;
                int cx = col - 1;
                if (cx < 0) cx = 1;
                if (cx > 127) cx = 126;
                float v = xb[(size_t)(chunk * 64 + cc) * HWn + (size_t)rows[kyb] * Wn + cx];
                __nv_bfloat16 h = __float2bfloat16(v);
                int o = kyb * C1_PLANE + col * ST + cc;
                XWh[o] = h;
                XWl[o] = __float2bfloat16(v - __bfloat162float(h));
            }
        }
        CP_WAIT0();
        __syncthreads();                      // weights visible + build visible + buf-reuse safe
        if (t + 1 < 36) cpW(t + 1, (t + 1) & 1);

        const uint32_t wbH = sb + C1_WBUF0 + (t & 1) * C1_WBUFSZ;
        const uint32_t wbL = wbH + C1_WHALF;
        const uint32_t ash = (uint32_t)((arow + kx) * ST + acol) * 2 + ky * C1_PLANEB;
#pragma unroll
        for (int ks = 0; ks < 4; ks++) {
            const uint32_t kb = ks * 32;
            uint32_t ah[8], al[8], bh[16], bl[16];
            ldsm_x4(ah,     sb + C1_XWH + ash + kb);
            ldsm_x4(ah + 4, sb + C1_XWH + ash + 16 * ST * 2 + kb);
            ldsm_x4(al,     sb + C1_XWL + ash + kb);
            ldsm_x4(al + 4, sb + C1_XWL + ash + 16 * ST * 2 + kb);
#pragma unroll
            for (int f = 0; f < 4; f++) {
                ldsm_x4(bh + 4 * f, wbH + boff + f * 16 * ST * 2 + kb);
                ldsm_x4(bl + 4 * f, wbL + boff + f * 16 * ST * 2 + kb);
            }
#pragma unroll
            for (int mi = 0; mi < 2; mi++) {
                const uint32_t* Ah = ah + 4 * mi;
                const uint32_t* Al = al + 4 * mi;
#pragma unroll
                for (int f = 0; f < 4; f++) {
                    mma_bf16(acc[mi][2 * f],     Ah, bh[4 * f],     bh[4 * f + 2]);
                    mma_bf16(acc[mi][2 * f],     Ah, bl[4 * f],     bl[4 * f + 2]);
                    mma_bf16(acc[mi][2 * f],     Al, bh[4 * f],     bh[4 * f + 2]);
                    mma_bf16(acc[mi][2 * f + 1], Ah, bh[4 * f + 1], bh[4 * f + 3]);
                    mma_bf16(acc[mi][2 * f + 1], Ah, bl[4 * f + 1], bl[4 * f + 3]);
                    mma_bf16(acc[mi][2 * f + 1], Al, bh[4 * f + 1], bh[4 * f + 3]);
                }
            }
        }
    }

    // epilogue: leaky -> split -> h1 [pix][mid] hi/lo
    const size_t slab = (size_t)(b * Hn + y) * Wn * MIDn;
    const int dr = lane >> 2, dc = (lane & 3) * 2;
#pragma unroll
    for (int mi = 0; mi < 2; mi++)
#pragma unroll
        for (int f = 0; f < 8; f++) {
            int pix = m0 + mi * 16 + dr, o = n0 + f * 8 + dc;
            float v0 = leaky(acc[mi][f][0]), v1 = leaky(acc[mi][f][1]);
            float v2 = leaky(acc[mi][f][2]), v3 = leaky(acc[mi][f][3]);
            size_t i1 = slab + (size_t)pix * MIDn + o;
            size_t i2 = slab + (size_t)(pix + 8) * MIDn + o;
            *(uint32_t*)(g_h1h + i1) = pack_hi(v0, v1);
            *(uint32_t*)(g_h1l + i1) = pack_lo(v0, v1);
            *(uint32_t*)(g_h1h + i2) = pack_hi(v2, v3);
            *(uint32_t*)(g_h1l + i2) = pack_lo(v2, v3);
        }
}

// ---------------- generic tile offsets for conv2 / attn ----------------
#define G_AH 0
#define G_AL 18432
#define G_BH 36864
#define G_BL 55296
#define G_SMEM 73728

// conv2: M=128 pix, N=128 o-half, K=128 mid.  Pure copies + MMA.
__global__ __launch_bounds__(256) void conv2_tc() {
    extern __shared__ char sm[];
    const uint32_t sb = smem_u32(sm);
    __nv_bfloat16* sAh = (__nv_bfloat16*)(sm + G_AH);
    __nv_bfloat16* sAl = (__nv_bfloat16*)(sm + G_AL);
    __nv_bfloat16* sBh = (__nv_bfloat16*)(sm + G_BH);
    __nv_bfloat16* sBl = (__nv_bfloat16*)(sm + G_BL);
    const int tid = threadIdx.x, lane = tid & 31, wid = tid >> 5;
    const int y = blockIdx.x, oh = blockIdx.y, b = blockIdx.z;
    const int m0 = (wid & 3) * 32, n0 = (wid >> 2) * 64;
    const uint32_t aoff = ((m0 + (lane & 15)) * ST + (lane >> 4) * 8) * 2;
    const uint32_t boff = ((n0 + (lane & 7) + ((lane >> 3) & 1) * 8) * ST + (lane >> 4) * 8) * 2;

    float acc[2][8][4];
#pragma unroll
    for (int mi = 0; mi < 2; mi++)
#pragma unroll
        for (int f = 0; f < 8; f++)
#pragma unroll
            for (int q = 0; q < 4; q++) acc[mi][f][q] = 0.f;

    const size_t h1slab = (size_t)(b * Hn + y) * Wn * MIDn;

    for (int kc = 0; kc < 128; kc += 64) {
        for (int i = tid; i < 1024; i += 256) {
            int row = i >> 3, q = i & 7;
            uint32_t so = row * ST + q * 8;
            *(uint4*)(sAh + so) = *(const uint4*)(g_h1h + h1slab + (size_t)row * MIDn + kc + q * 8);
            *(uint4*)(sAl + so) = *(const uint4*)(g_h1l + h1slab + (size_t)row * MIDn + kc + q * 8);
            *(uint4*)(sBh + so) = *(const uint4*)(g_w2h + (size_t)(oh * 128 + row) * MIDn + kc + q * 8);
            *(uint4*)(sBl + so) = *(const uint4*)(g_w2l + (size_t)(oh * 128 + row) * MIDn + kc + q * 8);
        }
        __syncthreads();
#pragma unroll
        for (int ks = 0; ks < 4; ks++) {
            const uint32_t kb = ks * 32;
            uint32_t ah[8], al[8], bh[16], bl[16];
            ldsm_x4(ah,     sb + G_AH + aoff + kb);
            ldsm_x4(ah + 4, sb + G_AH + aoff + 16 * ST * 2 + kb);
            ldsm_x4(al,     sb + G_AL + aoff + kb);
            ldsm_x4(al + 4, sb + G_AL + aoff + 16 * ST * 2 + kb);
#pragma unroll
            for (int f = 0; f < 4; f++) {
                ldsm_x4(bh + 4 * f, sb + G_BH + boff + f * 16 * ST * 2 + kb);
                ldsm_x4(bl + 4 * f, sb + G_BL + boff + f * 16 * ST * 2 + kb);
            }
#pragma unroll
            for (int mi = 0; mi < 2; mi++) {
                const uint32_t* Ah = ah + 4 * mi;
                const uint32_t* Al = al + 4 * mi;
#pragma unroll
                for (int f = 0; f < 4; f++) {
                    mma_bf16(acc[mi][2 * f],     Ah, bh[4 * f],     bh[4 * f + 2]);
                    mma_bf16(acc[mi][2 * f],     Ah, bl[4 * f],     bl[4 * f + 2]);
                    mma_bf16(acc[mi][2 * f],     Al, bh[4 * f],     bh[4 * f + 2]);
                    mma_bf16(acc[mi][2 * f + 1], Ah, bh[4 * f + 1], bh[4 * f + 3]);
                    mma_bf16(acc[mi][2 * f + 1], Ah, bl[4 * f + 1], bl[4 * f + 3]);
                    mma_bf16(acc[mi][2 * f + 1], Al, bh[4 * f + 1], bh[4 * f + 3]);
                }
            }
        }
        __syncthreads();
    }

    // epilogue: leaky -> xc32 + xc hi/lo, layout [pix][256 c]
    const size_t xslab = (size_t)(b * Hn + y) * Wn * Cn;
    const int dr = lane >> 2, dc = (lane & 3) * 2;
#pragma unroll
    for (int mi = 0; mi < 2; mi++)
#pragma unroll
        for (int f = 0; f < 8; f++) {
            int pix = m0 + mi * 16 + dr, c = oh * 128 + n0 + f * 8 + dc;
            float v0 = leaky(acc[mi][f][0]), v1 = leaky(acc[mi][f][1]);
            float v2 = leaky(acc[mi][f][2]), v3 = leaky(acc[mi][f][3]);
            size_t i1 = xslab + (size_t)pix * Cn + c;
            size_t i2 = xslab + (size_t)(pix + 8) * Cn + c;
            *(float2*)(g_xc32 + i1) = make_float2(v0, v1);
            *(float2*)(g_xc32 + i2) = make_float2(v2, v3);
            *(uint32_t*)(g_xch + i1) = pack_hi(v0, v1);
            *(uint32_t*)(g_xcl + i1) = pack_lo(v0, v1);
            *(uint32_t*)(g_xch + i2) = pack_hi(v2, v3);
            *(uint32_t*)(g_xcl + i2) = pack_lo(v2, v3);
        }
}

// ---------------- pool (2-stage, deterministic) ----------------
__global__ void pool1_kernel() {
    const int sl = blockIdx.x, b = blockIdx.y, tid = threadIdx.x;
    const float* base = g_xc32 + ((size_t)b * HWn + sl * 256) * Cn;
    float s = 0.f;
    for (int p = 0; p < 256; p++) s += base[(size_t)p * Cn + tid];
    g_ppart[(b * 64 + sl) * Cn + tid] = s;
}
__global__ void pool2_kernel() {
    const int b = blockIdx.x, tid = threadIdx.x;
    float s = 0.f;
    for (int i = 0; i < 64; i++) s += g_ppart[(b * 64 + i) * Cn + tid];
    g_pooled[b * Cn + tid] = s * (1.0f / (float)HWn);
}

// ---------------- MLP + outer score + softmax (bf16 split out, [b][c][e]) ----------------
__global__ void mlp_score_kernel(const float* __restrict__ w1, const float* __restrict__ b1,
                                 const float* __restrict__ w2, const float* __restrict__ b2) {
    const int b = blockIdx.x, tid = threadIdx.x;
    __shared__ float sp[256], sh[64], sm_[256];
    sp[tid] = g_pooled[b * 256 + tid];
    __syncthreads();
    if (tid < 64) {
        float s = b1[tid];
        for (int c = 0; c < 256; c++) s += sp[c] * w1[tid * 256 + c];
        sh[tid] = leaky(s);
    }
    __syncthreads();
    {
        float s = b2[tid];
        for (int j = 0; j < 64; j++) s += sh[j] * w2[tid * 64 + j];
        sm_[tid] = s;
    }
    __syncthreads();
    const int lane = tid & 31, w = tid >> 5;
    for (int r = w; r < 256; r += 8) {
        float mr = sm_[r];
        float mx = -1e30f;
        for (int e = lane; e < 256; e += 32) mx = fmaxf(mx, mr * sm_[e]);
        for (int off = 16; off; off >>= 1) mx = fmaxf(mx, __shfl_xor_sync(~0u, mx, off));
        float sum = 0.f;
        for (int e = lane; e < 256; e += 32) sum += expf(mr * sm_[e] - mx);
        for (int off = 16; off; off >>= 1) sum += __shfl_xor_sync(~0u, sum, off);
        float inv = 1.0f / sum;
        for (int e = lane; e < 256; e += 32) {
            float s = expf(mr * sm_[e] - mx) * inv;
            __nv_bfloat16 h = __float2bfloat16(s);
            size_t off2 = ((size_t)b * 256 + r) * 256 + e;
            g_scoreH[off2] = h;
            g_scoreL[off2] = __float2bfloat16(s - __bfloat162float(h));
        }
    }
}

// ---------------- attn: M=128 pix, N=128 c-half, K=256 e; + residual; smem transpose ----------------
__global__ __launch_bounds__(256) void attn_tc(float* __restrict__ out) {
    extern __shared__ char sm[];
    const uint32_t sb = smem_u32(sm);
    __nv_bfloat16* sAh = (__nv_bfloat16*)(sm + G_AH);
    __nv_bfloat16* sAl = (__nv_bfloat16*)(sm + G_AL);
    __nv_bfloat16* sBh = (__nv_bfloat16*)(sm + G_BH);
    __nv_bfloat16* sBl = (__nv_bfloat16*)(sm + G_BL);
    const int tid = threadIdx.x, lane = tid & 31, wid = tid >> 5;
    const int y = blockIdx.x, mh = blockIdx.y, b = blockIdx.z;
    const int m0 = (wid & 3) * 32, n0 = (wid >> 2) * 64;
    const uint32_t aoff = ((m0 + (lane & 15)) * ST + (lane >> 4) * 8) * 2;
    const uint32_t boff = ((n0 + (lane & 7) + ((lane >> 3) & 1) * 8) * ST + (lane >> 4) * 8) * 2;

    float acc[2][8][4];
#pragma unroll
    for (int mi = 0; mi < 2; mi++)
#pragma unroll
        for (int f = 0; f < 8; f++)
#pragma unroll
            for (int q = 0; q < 4; q++) acc[mi][f][q] = 0.f;

    const size_t xslab = (size_t)(b * Hn + y) * Wn * Cn;

    for (int kc = 0; kc < 256; kc += 64) {
        for (int i = tid; i < 1024; i += 256) {
            int row = i >> 3, q = i & 7;
            uint32_t so = row * ST + q * 8;
            *(uint4*)(sAh + so) = *(const uint4*)(g_xch + xslab + (size_t)row * Cn + kc + q * 8);
            *(uint4*)(sAl + so) = *(const uint4*)(g_xcl + xslab + (size_t)row * Cn + kc + q * 8);
            *(uint4*)(sBh + so) = *(const uint4*)(g_scoreH + ((size_t)b * 256 + mh * 128 + row) * 256 + kc + q * 8);
            *(uint4*)(sBl + so) = *(const uint4*)(g_scoreL + ((size_t)b * 256 + mh * 128 + row) * 256 + kc + q * 8);
        }
        __syncthreads();
#pragma unroll
        for (int ks = 0; ks < 4; ks++) {
            const uint32_t kb = ks * 32;
            uint32_t ah[8], al[8], bh[16], bl[16];
            ldsm_x4(ah,     sb + G_AH + aoff + kb);
            ldsm_x4(ah + 4, sb + G_AH + aoff + 16 * ST * 2 + kb);
            ldsm_x4(al,     sb + G_AL + aoff + kb);
            ldsm_x4(al + 4, sb + G_AL + aoff + 16 * ST * 2 + kb);
#pragma unroll
            for (int f = 0; f < 4; f++) {
                ldsm_x4(bh + 4 * f, sb + G_BH + boff + f * 16 * ST * 2 + kb);
                ldsm_x4(bl + 4 * f, sb + G_BL + boff + f * 16 * ST * 2 + kb);
            }
#pragma unroll
            for (int mi = 0; mi < 2; mi++) {
                const uint32_t* Ah = ah + 4 * mi;
                const uint32_t* Al = al + 4 * mi;
#pragma unroll
                for (int f = 0; f < 4; f++) {
                    mma_bf16(acc[mi][2 * f],     Ah, bh[4 * f],     bh[4 * f + 2]);
                    mma_bf16(acc[mi][2 * f],     Ah, bl[4 * f],     bl[4 * f + 2]);
                    mma_bf16(acc[mi][2 * f],     Al, bh[4 * f],     bh[4 * f + 2]);
                    mma_bf16(acc[mi][2 * f + 1], Ah, bh[4 * f + 1], bh[4 * f + 3]);
                    mma_bf16(acc[mi][2 * f + 1], Ah, bl[4 * f + 1], bl[4 * f + 3]);
                    mma_bf16(acc[mi][2 * f + 1], Al, bh[4 * f + 1], bh[4 * f + 3]);
                }
            }
        }
        __syncthreads();
    }

    // residual add + smem transpose -> coalesced NCHW stores
    float* sT = (float*)sm;   // [c 128][pix 132]
    const int dr = lane >> 2, dc = (lane & 3) * 2;
#pragma unroll
    for (int mi = 0; mi < 2; mi++)
#pragma unroll
        for (int f = 0; f < 8; f++) {
            int pix = m0 + mi * 16 + dr, c = n0 + f * 8 + dc;
            float2 r1 = *(const float2*)(g_xc32 + xslab + (size_t)pix * Cn + mh * 128 + c);
            float2 r2 = *(const float2*)(g_xc32 + xslab + (size_t)(pix + 8) * Cn + mh * 128 + c);
            sT[c * 132 + pix]           = acc[mi][f][0] + r1.x;
            sT[(c + 1) * 132 + pix]     = acc[mi][f][1] + r1.y;
            sT[c * 132 + pix + 8]       = acc[mi][f][2] + r2.x;
            sT[(c + 1) * 132 + pix + 8] = acc[mi][f][3] + r2.y;
        }
    __syncthreads();
    for (int i = tid; i < 16384; i += 256) {
        int c = i >> 7, p = i & 127;
        out[((size_t)(b * 256 + mh * 128 + c) * Hn + y) * Wn + p] = sT[c * 132 + p];
    }
}

// ---------------- launcher ----------------
extern "C" void kernel_launch(void* const* d_in, const int* in_sizes, int n_in,
                              void* d_out, int out_size) {
    const float* x   = (const float*)d_in[0];
    const float* c1w = (const float*)d_in[1];
    const float* c2w = (const float*)d_in[2];
    const float* mw1 = (const float*)d_in[3];
    const float* mb1 = (const float*)d_in[4];
    const float* mw2 = (const float*)d_in[5];
    const float* mb2 = (const float*)d_in[6];
    float* out = (float*)d_out;

    cudaFuncSetAttribute(conv1_tc, cudaFuncAttributeMaxDynamicSharedMemorySize, C1_SMEM);
    cudaFuncSetAttribute(conv2_tc, cudaFuncAttributeMaxDynamicSharedMemorySize, G_SMEM);
    cudaFuncSetAttribute(attn_tc,  cudaFuncAttributeMaxDynamicSharedMemorySize, G_SMEM);

    prep_kernel<<<1152, 256>>>(c1w, c2w);
    conv1_tc<<<dim3(Hn, Bn), 256, C1_SMEM>>>(x);
    conv2_tc<<<dim3(Hn, 2, Bn), 256, G_SMEM>>>();
    pool1_kernel<<<dim3(64, Bn), 256>>>();
    pool2_kernel<<<Bn, 256>>>();
    mlp_score_kernel<<<Bn, 256>>>(mw1, mb1, mw2, mb2);
    attn_tc<<<dim3(Hn, 2, Bn), 256, G_SMEM>>>(out);
}

// round 5
// speedup vs baseline: 2.3224x; 1.1725x over previous
#include <cuda_runtime.h>
#include <cuda_bf16.h>
#include <cstdint>
#include <math.h>

#define Bn   16
#define Cn   256
#define MIDn 128
#define Hn   128
#define Wn   128
#define HWn  (Hn*Wn)
#define ST   72

// ================= warp-MMA helpers =================
__device__ __forceinline__ uint32_t smem_u32(const void* p) {
    uint32_t a;
    asm("{ .reg .u64 t; cvta.to.shared.u64 t, %1; cvt.u32.u64 %0, t; }" : "=r"(a) : "l"(p));
    return a;
}
__device__ __forceinline__ void ldsm_x4(uint32_t* r, uint32_t addr) {
    asm volatile("ldmatrix.sync.aligned.m8n8.x4.shared.b16 {%0,%1,%2,%3}, [%4];"
                 : "=r"(r[0]), "=r"(r[1]), "=r"(r[2]), "=r"(r[3]) : "r"(addr));
}
__device__ __forceinline__ void mma_bf16(float* d, const uint32_t* a, uint32_t b0, uint32_t b1) {
    asm volatile("mma.sync.aligned.m16n8k16.row.col.f32.bf16.bf16.f32 "
                 "{%0,%1,%2,%3}, {%4,%5,%6,%7}, {%8,%9}, {%0,%1,%2,%3};"
                 : "+f"(d[0]), "+f"(d[1]), "+f"(d[2]), "+f"(d[3])
                 : "r"(a[0]), "r"(a[1]), "r"(a[2]), "r"(a[3]), "r"(b0), "r"(b1));
}
__device__ __forceinline__ void cp16(uint32_t saddr, const void* g) {
    asm volatile("cp.async.cg.shared.global [%0], [%1], 16;" :: "r"(saddr), "l"(g) : "memory");
}
#define CP_COMMIT() asm volatile("cp.async.commit_group;" ::: "memory")
#define CP_WAIT0()  asm volatile("cp.async.wait_group 0;" ::: "memory")
__device__ __forceinline__ float leaky(float v) { return v >= 0.f ? v : 0.2f * v; }
__device__ __forceinline__ uint32_t pack_hi(float a, float b) {
    __nv_bfloat16 h0 = __float2bfloat16(a), h1 = __float2bfloat16(b);
    return (uint32_t)__bfloat16_as_ushort(h0) | ((uint32_t)__bfloat16_as_ushort(h1) << 16);
}
__device__ __forceinline__ uint32_t pack_lo(float a, float b) {
    __nv_bfloat16 h0 = __float2bfloat16(a), h1 = __float2bfloat16(b);
    __nv_bfloat16 l0 = __float2bfloat16(a - __bfloat162float(h0));
    __nv_bfloat16 l1 = __float2bfloat16(b - __bfloat162float(h1));
    return (uint32_t)__bfloat16_as_ushort(l0) | ((uint32_t)__bfloat16_as_ushort(l1) << 16);
}

// ================= scratch =================
__device__ __nv_bfloat16 g_w1h[4 * 9 * 128 * 64];   // [chunk*9+tap][o][cc]
__device__ __nv_bfloat16 g_w1l[4 * 9 * 128 * 64];
__device__ __nv_bfloat16 g_w2h[256 * 128];          // [o][mid]
__device__ __nv_bfloat16 g_w2l[256 * 128];
__device__ __nv_bfloat16 g_h1h[(size_t)Bn * HWn * MIDn];   // [b][pixlin][mid]
__device__ __nv_bfloat16 g_h1l[(size_t)Bn * HWn * MIDn];
__device__ __nv_bfloat16 g_xch[(size_t)Bn * HWn * Cn];     // [b][pixlin][c]
__device__ __nv_bfloat16 g_xcl[(size_t)Bn * HWn * Cn];
__device__ float g_ppart[Bn * 64 * 2 * 128];               // [b][yb][oh][128]
__device__ float g_pooled[Bn * Cn];
__device__ __nv_bfloat16 g_scoreH[(size_t)Bn * Cn * Cn];   // [b][c][e]
__device__ __nv_bfloat16 g_scoreL[(size_t)Bn * Cn * Cn];

// ---------------- kernel 0: weight prep ----------------
__global__ void prep_kernel(const float* __restrict__ w1, const float* __restrict__ w2) {
    int idx = blockIdx.x * 256 + threadIdx.x;
    if (idx < 128 * 256 * 9) {
        int o = idx / 2304, rem = idx - o * 2304;
        int c = rem / 9, tap = rem - c * 9;
        float w = w1[idx];
        __nv_bfloat16 h = __float2bfloat16(w);
        __nv_bfloat16 l = __float2bfloat16(w - __bfloat162float(h));
        int chunk = c >> 6, cc = c & 63;
        int off = (((chunk * 9 + tap) << 7) + o) * 64 + cc;
        g_w1h[off] = h;
        g_w1l[off] = l;
    }
    if (idx < 256 * 128) {
        float w = w2[idx];
        __nv_bfloat16 h = __float2bfloat16(w);
        g_w2h[idx] = h;
        g_w2l[idx] = __float2bfloat16(w - __bfloat162float(h));
    }
}

// ---------------- conv1: M=256 pix (2 rows), N=128 o, K=36*64 ----------------
#define C1_PLANE  (132 * ST)                 // elems/plane
#define C1_PLANEB (C1_PLANE * 2)             // 19008 B
#define C1_XWH    0
#define C1_XWL    (4 * C1_PLANEB)            // 76032
#define C1_WBUF0  (2 * C1_XWL)               // 152064
#define C1_WHALF  18432
#define C1_WBUFSZ 36864
#define C1_SMEM   (C1_WBUF0 + 2 * C1_WBUFSZ) // 225792

__global__ __launch_bounds__(512, 1) void conv1_tc(const float* __restrict__ x) {
    extern __shared__ char sm[];
    const uint32_t sb = smem_u32(sm);
    const int tid = threadIdx.x, lane = tid & 31, wid = tid >> 5;
    const int yb = blockIdx.x, b = blockIdx.y;
    const int y0 = yb * 2;
    const int m0w = (wid & 3) * 64, n0 = (wid >> 2) * 32;
    const int yw = m0w >> 7;
    const uint32_t aoff = (uint32_t)(((m0w & 127) + (lane & 15)) * ST + (lane >> 4) * 8) * 2;
    const uint32_t boff = (uint32_t)((n0 + (lane & 7) + ((lane >> 3) & 1) * 8) * ST + (lane >> 4) * 8) * 2;

    float acc[4][2][2][4];
#pragma unroll
    for (int mi = 0; mi < 4; mi++)
#pragma unroll
        for (int f = 0; f < 2; f++)
#pragma unroll
            for (int ns = 0; ns < 2; ns++)
#pragma unroll
                for (int q = 0; q < 4; q++) acc[mi][f][ns][q] = 0.f;

    int ry[4];
#pragma unroll
    for (int pl = 0; pl < 4; pl++) {
        int r = y0 - 1 + pl;
        if (r < 0) r = 1;
        if (r > 127) r = 126;
        ry[pl] = r;
    }
    const float* xb = x + (size_t)b * Cn * HWn;
    __nv_bfloat16* XWh = (__nv_bfloat16*)(sm + C1_XWH);
    __nv_bfloat16* XWl = (__nv_bfloat16*)(sm + C1_XWL);

    auto cpW = [&](int gidx, int buf) {
        uint32_t dst = sb + C1_WBUF0 + buf * C1_WBUFSZ;
        const uint4* srcH = (const uint4*)(g_w1h + ((size_t)gidx << 13));
        const uint4* srcL = (const uint4*)(g_w1l + ((size_t)gidx << 13));
        for (int i = tid; i < 1024; i += 512) {
            int row = i >> 3, q = i & 7;
            uint32_t so = (uint32_t)(row * ST + q * 8) * 2;
            cp16(dst + so, srcH + i);
            cp16(dst + C1_WHALF + so, srcL + i);
        }
        CP_COMMIT();
    };
    cpW(0, 0);

    for (int t = 0; t < 36; t++) {
        const int chunk = t / 9, tap = t - chunk * 9;
        const int ky = tap / 3, kx = tap - ky * 3;
        if (tap == 0) {
            __syncthreads();
            for (int idx = tid; idx < 64 * 520; idx += 512) {
                int cc = idx / 520, r = idx - cc * 520;
                int pl = r / 130, col = r - pl * 130;
                int cx = col - 1;
                if (cx < 0) cx = 1;
                if (cx > 127) cx = 126;
                float v = xb[(size_t)(chunk * 64 + cc) * HWn + (size_t)ry[pl] * Wn + cx];
                __nv_bfloat16 h = __float2bfloat16(v);
                int o = pl * C1_PLANE + col * ST + cc;
                XWh[o] = h;
                XWl[o] = __float2bfloat16(v - __bfloat162float(h));
            }
        }
        CP_WAIT0();
        __syncthreads();
        if (t + 1 < 36) cpW(t + 1, (t + 1) & 1);

        const uint32_t wbH = sb + C1_WBUF0 + (t & 1) * C1_WBUFSZ;
        const uint32_t wbL = wbH + C1_WHALF;
        const uint32_t aB  = sb + C1_XWH + (ky + yw) * C1_PLANEB + kx * (ST * 2) + aoff;
        const uint32_t aBl = aB + (C1_XWL - C1_XWH);
#pragma unroll
        for (int ks = 0; ks < 4; ks++) {
            const uint32_t kb = ks * 32;
            uint32_t bhm[8], blm[8];
            ldsm_x4(bhm,     wbH + boff + kb);
            ldsm_x4(bhm + 4, wbH + boff + 16 * ST * 2 + kb);
            ldsm_x4(blm,     wbL + boff + kb);
            ldsm_x4(blm + 4, wbL + boff + 16 * ST * 2 + kb);
#pragma unroll
            for (int mi = 0; mi < 4; mi++) {
                uint32_t ah[4], al[4];
                ldsm_x4(ah, aB  + mi * 16 * ST * 2 + kb);
                ldsm_x4(al, aBl + mi * 16 * ST * 2 + kb);
#pragma unroll
                for (int f = 0; f < 2; f++) {
                    mma_bf16(acc[mi][f][0], ah, bhm[4 * f],     bhm[4 * f + 2]);
                    mma_bf16(acc[mi][f][0], ah, blm[4 * f],     blm[4 * f + 2]);
                    mma_bf16(acc[mi][f][0], al, bhm[4 * f],     bhm[4 * f + 2]);
                    mma_bf16(acc[mi][f][1], ah, bhm[4 * f + 1], bhm[4 * f + 3]);
                    mma_bf16(acc[mi][f][1], ah, blm[4 * f + 1], blm[4 * f + 3]);
                    mma_bf16(acc[mi][f][1], al, bhm[4 * f + 1], bhm[4 * f + 3]);
                }
            }
        }
    }

    // epilogue: leaky -> split -> h1 [pixlin][mid]
    const int dr = lane >> 2, dc = (lane & 3) * 2;
    const size_t slab = ((size_t)b * HWn + (size_t)y0 * Wn);
#pragma unroll
    for (int mi = 0; mi < 4; mi++)
#pragma unroll
        for (int f = 0; f < 2; f++)
#pragma unroll
            for (int ns = 0; ns < 2; ns++) {
                int pix = m0w + mi * 16 + dr;
                int o = n0 + f * 16 + ns * 8 + dc;
                float v0 = leaky(acc[mi][f][ns][0]), v1 = leaky(acc[mi][f][ns][1]);
                float v2 = leaky(acc[mi][f][ns][2]), v3 = leaky(acc[mi][f][ns][3]);
                size_t i1 = (slab + pix) * MIDn + o;
                size_t i2 = (slab + pix + 8) * MIDn + o;
                *(uint32_t*)(g_h1h + i1) = pack_hi(v0, v1);
                *(uint32_t*)(g_h1l + i1) = pack_lo(v0, v1);
                *(uint32_t*)(g_h1h + i2) = pack_hi(v2, v3);
                *(uint32_t*)(g_h1l + i2) = pack_lo(v2, v3);
            }
}

// ---------------- conv2: M=256 pix, N=128 o-half, K=128; + fused pool partials ----------------
#define G_AH 0
#define G_AL 36864
#define G_BH 73728
#define G_BL 92160
#define G_PR 110592
#define G_SMEM (G_PR + 512)

__global__ __launch_bounds__(512, 1) void conv2_tc() {
    extern __shared__ char sm[];
    const uint32_t sb = smem_u32(sm);
    __nv_bfloat16* sAh = (__nv_bfloat16*)(sm + G_AH);
    __nv_bfloat16* sAl = (__nv_bfloat16*)(sm + G_AL);
    __nv_bfloat16* sBh = (__nv_bfloat16*)(sm + G_BH);
    __nv_bfloat16* sBl = (__nv_bfloat16*)(sm + G_BL);
    float* pr = (float*)(sm + G_PR);
    const int tid = threadIdx.x, lane = tid & 31, wid = tid >> 5;
    const int yb = blockIdx.x, oh = blockIdx.y, b = blockIdx.z;
    const int m0w = (wid & 3) * 64, n0 = (wid >> 2) * 32;
    const uint32_t aoff = (uint32_t)((m0w + (lane & 15)) * ST + (lane >> 4) * 8) * 2;
    const uint32_t boff = (uint32_t)((n0 + (lane & 7) + ((lane >> 3) & 1) * 8) * ST + (lane >> 4) * 8) * 2;

    float acc[4][2][2][4];
#pragma unroll
    for (int mi = 0; mi < 4; mi++)
#pragma unroll
        for (int f = 0; f < 2; f++)
#pragma unroll
            for (int ns = 0; ns < 2; ns++)
#pragma unroll
                for (int q = 0; q < 4; q++) acc[mi][f][ns][q] = 0.f;

    const size_t slab = (size_t)b * HWn + (size_t)yb * 256;

    for (int kc = 0; kc < 128; kc += 64) {
        for (int i = tid; i < 2048; i += 512) {
            int row = i >> 3, q = i & 7;
            uint32_t so = row * ST + q * 8;
            *(uint4*)(sAh + so) = *(const uint4*)(g_h1h + (slab + row) * MIDn + kc + q * 8);
            *(uint4*)(sAl + so) = *(const uint4*)(g_h1l + (slab + row) * MIDn + kc + q * 8);
            if (i < 1024) {
                *(uint4*)(sBh + so) = *(const uint4*)(g_w2h + (size_t)(oh * 128 + row) * MIDn + kc + q * 8);
                *(uint4*)(sBl + so) = *(const uint4*)(g_w2l + (size_t)(oh * 128 + row) * MIDn + kc + q * 8);
            }
        }
        __syncthreads();
#pragma unroll
        for (int ks = 0; ks < 4; ks++) {
            const uint32_t kb = ks * 32;
            uint32_t bhm[8], blm[8];
            ldsm_x4(bhm,     sb + G_BH + boff + kb);
            ldsm_x4(bhm + 4, sb + G_BH + boff + 16 * ST * 2 + kb);
            ldsm_x4(blm,     sb + G_BL + boff + kb);
            ldsm_x4(blm + 4, sb + G_BL + boff + 16 * ST * 2 + kb);
#pragma unroll
            for (int mi = 0; mi < 4; mi++) {
                uint32_t ah[4], al[4];
                ldsm_x4(ah, sb + G_AH + aoff + mi * 16 * ST * 2 + kb);
                ldsm_x4(al, sb + G_AL + aoff + mi * 16 * ST * 2 + kb);
#pragma unroll
                for (int f = 0; f < 2; f++) {
                    mma_bf16(acc[mi][f][0], ah, bhm[4 * f],     bhm[4 * f + 2]);
                    mma_bf16(acc[mi][f][0], ah, blm[4 * f],     blm[4 * f + 2]);
                    mma_bf16(acc[mi][f][0], al, bhm[4 * f],     bhm[4 * f + 2]);
                    mma_bf16(acc[mi][f][1], ah, bhm[4 * f + 1], bhm[4 * f + 3]);
                    mma_bf16(acc[mi][f][1], ah, blm[4 * f + 1], blm[4 * f + 3]);
                    mma_bf16(acc[mi][f][1], al, bhm[4 * f + 1], bhm[4 * f + 3]);
                }
            }
        }
        __syncthreads();
    }

    // epilogue: leaky -> xc hi/lo; pool partials via smem atomics
    if (tid < 128) pr[tid] = 0.f;
    __syncthreads();
    const int dr = lane >> 2, dc = (lane & 3) * 2;
#pragma unroll
    for (int f = 0; f < 2; f++)
#pragma unroll
        for (int ns = 0; ns < 2; ns++) {
            int cl = n0 + f * 16 + ns * 8 + dc;
            float s0 = 0.f, s1 = 0.f;
#pragma unroll
            for (int mi = 0; mi < 4; mi++) {
                int pix = m0w + mi * 16 + dr;
                float v0 = leaky(acc[mi][f][ns][0]), v1 = leaky(acc[mi][f][ns][1]);
                float v2 = leaky(acc[mi][f][ns][2]), v3 = leaky(acc[mi][f][ns][3]);
                size_t i1 = (slab + pix) * Cn + oh * 128 + cl;
                size_t i2 = (slab + pix + 8) * Cn + oh * 128 + cl;
                *(uint32_t*)(g_xch + i1) = pack_hi(v0, v1);
                *(uint32_t*)(g_xcl + i1) = pack_lo(v0, v1);
                *(uint32_t*)(g_xch + i2) = pack_hi(v2, v3);
                *(uint32_t*)(g_xcl + i2) = pack_lo(v2, v3);
                s0 += v0 + v2;
                s1 += v1 + v3;
            }
            atomicAdd(&pr[cl], s0);
            atomicAdd(&pr[cl + 1], s1);
        }
    __syncthreads();
    if (tid < 128)
        g_ppart[(((size_t)b * 64 + yb) * 2 + oh) * 128 + tid] = pr[tid];
}

// ---------------- pool2 ----------------
__global__ void pool2_kernel() {
    const int b = blockIdx.x, tid = threadIdx.x;
    const int oh = tid >> 7, cl = tid & 127;
    float s = 0.f;
    for (int yb = 0; yb < 64; yb++)
        s += g_ppart[(((size_t)b * 64 + yb) * 2 + oh) * 128 + cl];
    g_pooled[b * Cn + tid] = s * (1.0f / (float)HWn);
}

// ---------------- MLP + outer score + softmax ----------------
__global__ void mlp_score_kernel(const float* __restrict__ w1, const float* __restrict__ b1,
                                 const float* __restrict__ w2, const float* __restrict__ b2) {
    const int b = blockIdx.x, tid = threadIdx.x;
    __shared__ float sp[256], sh[64], sm_[256];
    sp[tid] = g_pooled[b * 256 + tid];
    __syncthreads();
    if (tid < 64) {
        float s = b1[tid];
        for (int c = 0; c < 256; c++) s += sp[c] * w1[tid * 256 + c];
        sh[tid] = leaky(s);
    }
    __syncthreads();
    {
        float s = b2[tid];
        for (int j = 0; j < 64; j++) s += sh[j] * w2[tid * 64 + j];
        sm_[tid] = s;
    }
    __syncthreads();
    const int lane = tid & 31, w = tid >> 5;
    for (int r = w; r < 256; r += 8) {
        float mr = sm_[r];
        float mx = -1e30f;
        for (int e = lane; e < 256; e += 32) mx = fmaxf(mx, mr * sm_[e]);
        for (int off = 16; off; off >>= 1) mx = fmaxf(mx, __shfl_xor_sync(~0u, mx, off));
        float sum = 0.f;
        for (int e = lane; e < 256; e += 32) sum += expf(mr * sm_[e] - mx);
        for (int off = 16; off; off >>= 1) sum += __shfl_xor_sync(~0u, sum, off);
        float inv = 1.0f / sum;
        for (int e = lane; e < 256; e += 32) {
            float s = expf(mr * sm_[e] - mx) * inv;
            __nv_bfloat16 h = __float2bfloat16(s);
            size_t off2 = ((size_t)b * 256 + r) * 256 + e;
            g_scoreH[off2] = h;
            g_scoreL[off2] = __float2bfloat16(s - __bfloat162float(h));
        }
    }
}

// ---------------- attn: M=256 pix, N=128 c-half, K=256; + residual + transpose ----------------
__global__ __launch_bounds__(512, 1) void attn_tc(float* __restrict__ out) {
    extern __shared__ char sm[];
    const uint32_t sb = smem_u32(sm);
    __nv_bfloat16* sAh = (__nv_bfloat16*)(sm + G_AH);
    __nv_bfloat16* sAl = (__nv_bfloat16*)(sm + G_AL);
    __nv_bfloat16* sBh = (__nv_bfloat16*)(sm + G_BH);
    __nv_bfloat16* sBl = (__nv_bfloat16*)(sm + G_BL);
    const int tid = threadIdx.x, lane = tid & 31, wid = tid >> 5;
    const int yb = blockIdx.x, mh = blockIdx.y, b = blockIdx.z;
    const int m0w = (wid & 3) * 64, n0 = (wid >> 2) * 32;
    const int yw = m0w >> 7;
    const uint32_t aoff = (uint32_t)((m0w + (lane & 15)) * ST + (lane >> 4) * 8) * 2;
    const uint32_t boff = (uint32_t)((n0 + (lane & 7) + ((lane >> 3) & 1) * 8) * ST + (lane >> 4) * 8) * 2;

    float acc[4][2][2][4];
#pragma unroll
    for (int mi = 0; mi < 4; mi++)
#pragma unroll
        for (int f = 0; f < 2; f++)
#pragma unroll
            for (int ns = 0; ns < 2; ns++)
#pragma unroll
                for (int q = 0; q < 4; q++) acc[mi][f][ns][q] = 0.f;

    const size_t slab = (size_t)b * HWn + (size_t)yb * 256;

    for (int kc = 0; kc < 256; kc += 64) {
        for (int i = tid; i < 2048; i += 512) {
            int row = i >> 3, q = i & 7;
            uint32_t so = row * ST + q * 8;
            *(uint4*)(sAh + so) = *(const uint4*)(g_xch + (slab + row) * Cn + kc + q * 8);
            *(uint4*)(sAl + so) = *(const uint4*)(g_xcl + (slab + row) * Cn + kc + q * 8);
            if (i < 1024) {
                *(uint4*)(sBh + so) = *(const uint4*)(g_scoreH + ((size_t)b * 256 + mh * 128 + row) * 256 + kc + q * 8);
                *(uint4*)(sBl + so) = *(const uint4*)(g_scoreL + ((size_t)b * 256 + mh * 128 + row) * 256 + kc + q * 8);
            }
        }
        __syncthreads();
#pragma unroll
        for (int ks = 0; ks < 4; ks++) {
            const uint32_t kb = ks * 32;
            uint32_t bhm[8], blm[8];
            ldsm_x4(bhm,     sb + G_BH + boff + kb);
            ldsm_x4(bhm + 4, sb + G_BH + boff + 16 * ST * 2 + kb);
            ldsm_x4(blm,     sb + G_BL + boff + kb);
            ldsm_x4(blm + 4, sb + G_BL + boff + 16 * ST * 2 + kb);
#pragma unroll
            for (int mi = 0; mi < 4; mi++) {
                uint32_t ah[4], al[4];
                ldsm_x4(ah, sb + G_AH + aoff + mi * 16 * ST * 2 + kb);
                ldsm_x4(al, sb + G_AL + aoff + mi * 16 * ST * 2 + kb);
#pragma unroll
                for (int f = 0; f < 2; f++) {
                    mma_bf16(acc[mi][f][0], ah, bhm[4 * f],     bhm[4 * f + 2]);
                    mma_bf16(acc[mi][f][0], ah, blm[4 * f],     blm[4 * f + 2]);
                    mma_bf16(acc[mi][f][0], al, bhm[4 * f],     bhm[4 * f + 2]);
                    mma_bf16(acc[mi][f][1], ah, bhm[4 * f + 1], bhm[4 * f + 3]);
                    mma_bf16(acc[mi][f][1], ah, blm[4 * f + 1], blm[4 * f + 3]);
                    mma_bf16(acc[mi][f][1], al, bhm[4 * f + 1], bhm[4 * f + 3]);
                }
            }
        }
        __syncthreads();
    }

    // residual + transpose, one y row at a time
    float* sT = (float*)sm;   // [128 c][132]
    const int dr = lane >> 2, dc = (lane & 3) * 2;
    for (int yw2 = 0; yw2 < 2; yw2++) {
        if (yw == yw2) {
#pragma unroll
            for (int mi = 0; mi < 4; mi++)
#pragma unroll
                for (int f = 0; f < 2; f++)
#pragma unroll
                    for (int ns = 0; ns < 2; ns++) {
                        int pix = m0w + mi * 16 + dr;
                        int c = n0 + f * 16 + ns * 8 + dc;
                        size_t i1 = (slab + pix) * Cn + mh * 128 + c;
                        size_t i2 = (slab + pix + 8) * Cn + mh * 128 + c;
                        float r0 = __bfloat162float(g_xch[i1])     + __bfloat162float(g_xcl[i1]);
                        float r1 = __bfloat162float(g_xch[i1 + 1]) + __bfloat162float(g_xcl[i1 + 1]);
                        float r2 = __bfloat162float(g_xch[i2])     + __bfloat162float(g_xcl[i2]);
                        float r3 = __bfloat162float(g_xch[i2 + 1]) + __bfloat162float(g_xcl[i2 + 1]);
                        int p = pix & 127;
                        sT[c * 132 + p]           = acc[mi][f][ns][0] + r0;
                        sT[(c + 1) * 132 + p]     = acc[mi][f][ns][1] + r1;
                        sT[c * 132 + p + 8]       = acc[mi][f][ns][2] + r2;
                        sT[(c + 1) * 132 + p + 8] = acc[mi][f][ns][3] + r3;
                    }
        }
        __syncthreads();
        for (int i = tid; i < 16384; i += 512) {
            int c = i >> 7, p = i & 127;
            out[(((size_t)b * 256 + mh * 128 + c) * Hn + yb * 2 + yw2) * Wn + p] = sT[c * 132 + p];
        }
        __syncthreads();
    }
}

// ---------------- launcher ----------------
extern "C" void kernel_launch(void* const* d_in, const int* in_sizes, int n_in,
                              void* d_out, int out_size) {
    const float* x   = (const float*)d_in[0];
    const float* c1w = (const float*)d_in[1];
    const float* c2w = (const float*)d_in[2];
    const float* mw1 = (const float*)d_in[3];
    const float* mb1 = (const float*)d_in[4];
    const float* mw2 = (const float*)d_in[5];
    const float* mb2 = (const float*)d_in[6];
    float* out = (float*)d_out;

    cudaFuncSetAttribute(conv1_tc, cudaFuncAttributeMaxDynamicSharedMemorySize, C1_SMEM);
    cudaFuncSetAttribute(conv2_tc, cudaFuncAttributeMaxDynamicSharedMemorySize, G_SMEM);
    cudaFuncSetAttribute(attn_tc,  cudaFuncAttributeMaxDynamicSharedMemorySize, G_SMEM);

    prep_kernel<<<1152, 256>>>(c1w, c2w);
    conv1_tc<<<dim3(64, Bn), 512, C1_SMEM>>>(x);
    conv2_tc<<<dim3(64, 2, Bn), 512, G_SMEM>>>();
    pool2_kernel<<<Bn, 256>>>();
    mlp_score_kernel<<<Bn, 256>>>(mw1, mb1, mw2, mb2);
    attn_tc<<<dim3(64, 2, Bn), 512, G_SMEM>>>(out);
}

// round 8
// speedup vs baseline: 2.6606x; 1.1457x over previous
#include <cuda_runtime.h>
#include <cuda_bf16.h>
#include <cstdint>
#include <math.h>

#define Bn   16
#define Cn   256
#define MIDn 128
#define Hn   128
#define Wn   128
#define HWn  (Hn*Wn)
#define ST   72

// ================= warp-MMA helpers =================
__device__ __forceinline__ uint32_t smem_u32(const void* p) {
    uint32_t a;
    asm("{ .reg .u64 t; cvta.to.shared.u64 t, %1; cvt.u32.u64 %0, t; }" : "=r"(a) : "l"(p));
    return a;
}
__device__ __forceinline__ void ldsm_x4(uint32_t* r, uint32_t addr) {
    asm volatile("ldmatrix.sync.aligned.m8n8.x4.shared.b16 {%0,%1,%2,%3}, [%4];"
                 : "=r"(r[0]), "=r"(r[1]), "=r"(r[2]), "=r"(r[3]) : "r"(addr));
}
__device__ __forceinline__ void mma_bf16(float* d, const uint32_t* a, uint32_t b0, uint32_t b1) {
    asm volatile("mma.sync.aligned.m16n8k16.row.col.f32.bf16.bf16.f32 "
                 "{%0,%1,%2,%3}, {%4,%5,%6,%7}, {%8,%9}, {%0,%1,%2,%3};"
                 : "+f"(d[0]), "+f"(d[1]), "+f"(d[2]), "+f"(d[3])
                 : "r"(a[0]), "r"(a[1]), "r"(a[2]), "r"(a[3]), "r"(b0), "r"(b1));
}
__device__ __forceinline__ float leaky(float v) { return v >= 0.f ? v : 0.2f * v; }
__device__ __forceinline__ uint32_t pack_hi(float a, float b) {
    __nv_bfloat16 h0 = __float2bfloat16(a), h1 = __float2bfloat16(b);
    return (uint32_t)__bfloat16_as_ushort(h0) | ((uint32_t)__bfloat16_as_ushort(h1) << 16);
}
__device__ __forceinline__ uint32_t pack_lo(float a, float b) {
    __nv_bfloat16 h0 = __float2bfloat16(a), h1 = __float2bfloat16(b);
    __nv_bfloat16 l0 = __float2bfloat16(a - __bfloat162float(h0));
    __nv_bfloat16 l1 = __float2bfloat16(b - __bfloat162float(h1));
    return (uint32_t)__bfloat16_as_ushort(l0) | ((uint32_t)__bfloat16_as_ushort(l1) << 16);
}

// ================= scratch =================
// conv1 weights pre-packed as mma.sync B-fragments:
// [tap 9][ch 8][ng 16][ks 2][lane 32] -> uint4 {b0h, b1h, b0l, b1l}
__device__ uint4 g_w1p[9 * 8 * 16 * 2 * 32];
__device__ __nv_bfloat16 g_w2h[256 * 128];          // [o][mid]
__device__ __nv_bfloat16 g_w2l[256 * 128];
__device__ __nv_bfloat16 g_h1h[(size_t)Bn * HWn * MIDn];   // [b][pixlin][mid]
__device__ __nv_bfloat16 g_h1l[(size_t)Bn * HWn * MIDn];
__device__ __nv_bfloat16 g_xch[(size_t)Bn * HWn * Cn];     // [b][pixlin][c]
__device__ __nv_bfloat16 g_xcl[(size_t)Bn * HWn * Cn];
__device__ float g_ppart[Bn * 64 * 2 * 128];
__device__ float g_pooled[Bn * Cn];
__device__ __nv_bfloat16 g_scoreH[(size_t)Bn * Cn * Cn];   // [b][c][e]
__device__ __nv_bfloat16 g_scoreL[(size_t)Bn * Cn * Cn];

// ---------------- kernel 0: weight prep ----------------
__global__ void prep_kernel(const float* __restrict__ w1, const float* __restrict__ w2) {
    int idx = blockIdx.x * 256 + threadIdx.x;   // 288*256 = 73728
    {
        int lane = idx & 31, ks = (idx >> 5) & 1, ng = (idx >> 6) & 15;
        int ch = (idx >> 10) & 7, tap = idx >> 13;
        int n = ng * 8 + (lane >> 2);                 // output channel o
        int c0 = ch * 32 + ks * 16 + (lane & 3) * 2;  // k (input channel)
        float wa = w1[n * 2304 + c0 * 9 + tap];
        float wb = w1[n * 2304 + (c0 + 1) * 9 + tap];
        float wc = w1[n * 2304 + (c0 + 8) * 9 + tap];
        float wd = w1[n * 2304 + (c0 + 9) * 9 + tap];
        uint4 v;
        v.x = pack_hi(wa, wb);
        v.y = pack_hi(wc, wd);
        v.z = pack_lo(wa, wb);
        v.w = pack_lo(wc, wd);
        g_w1p[idx] = v;
    }
    if (idx < 256 * 128) {
        float w = w2[idx];
        __nv_bfloat16 h = __float2bfloat16(w);
        g_w2h[idx] = h;
        g_w2l[idx] = __float2bfloat16(w - __bfloat162float(h));
    }
}

// ---------------- conv1: M=256 pix (2 rows), N=128 o, K=8 chunks x 9 taps x 32 ----------------
// Window geometry (ALL BYTES): row = 32 k-elems (64 B) + 16 B pad = 80 B.
// plane = 132 rows x 80 B; hi half = 4 planes; buffer = hi+lo; double-buffered.
#define C1_ROWB  80
#define C1_PLB   (132 * C1_ROWB)               // 10560
#define C1_HALF  (4 * C1_PLB)                  // 42240
#define C1_BUF   (2 * C1_HALF)                 // 84480
#define C1_SMEM  (2 * C1_BUF)                  // 168960

__global__ __launch_bounds__(512, 1) void conv1_tc(const float* __restrict__ x) {
    extern __shared__ char sm[];
    const uint32_t sb = smem_u32(sm);
    const int tid = threadIdx.x, lane = tid & 31, wid = tid >> 5;
    const int yb = blockIdx.x, b = blockIdx.y;
    const int y0 = yb * 2;
    const int m0w = (wid & 3) * 64;            // pixel-group base (0..255)
    const int n0g = (wid >> 2) * 4;            // ngroup base (n0 = n0g*8)
    const int yw = m0w >> 7;                   // which image row (0/1)
    const uint32_t aoff_lane = (uint32_t)((lane & 15) * C1_ROWB + (lane >> 4) * 16);

    float acc[4][4][4];
#pragma unroll
    for (int mi = 0; mi < 4; mi++)
#pragma unroll
        for (int j = 0; j < 4; j++)
#pragma unroll
            for (int q = 0; q < 4; q++) acc[mi][j][q] = 0.f;

    int ry[4];
#pragma unroll
    for (int pl = 0; pl < 4; pl++) {
        int r = y0 - 1 + pl;
        if (r < 0) r = 1;
        if (r > 127) r = 126;
        ry[pl] = r;
    }
    const float* xb = x + (size_t)b * Cn * HWn;

    // stage chunk ch (32 channels) into buffer buf
    auto stage = [&](int ch, int buf) {
        char* WH = sm + buf * C1_BUF;
        char* WL = WH + C1_HALF;
        for (int idx = tid; idx < 32 * 520; idx += 512) {
            int cc = idx / 520, r = idx - cc * 520;
            int pl = r / 130, col = r - pl * 130;
            int cx = col - 1;
            if (cx < 0) cx = 1;
            if (cx > 127) cx = 126;
            float v = xb[(size_t)(ch * 32 + cc) * HWn + (size_t)ry[pl] * Wn + cx];
            __nv_bfloat16 h = __float2bfloat16(v);
            int off = pl * C1_PLB + col * C1_ROWB + cc * 2;
            *(__nv_bfloat16*)(WH + off) = h;
            *(__nv_bfloat16*)(WL + off) = __float2bfloat16(v - __bfloat162float(h));
        }
    };

    stage(0, 0);
    __syncthreads();

    for (int ch = 0; ch < 8; ch++) {
        const int buf = ch & 1;
        const uint32_t WHb = sb + buf * C1_BUF;
        const uint32_t WLb = WHb + C1_HALF;
#pragma unroll
        for (int tap = 0; tap < 9; tap++) {
            const int ky = tap / 3, kx = tap - ky * 3;
            const uint32_t pbase = (uint32_t)((ky + yw) * C1_PLB) +
                                   (uint32_t)(((m0w & 127) + kx) * C1_ROWB) + aoff_lane;
            const uint4* wp = g_w1p + ((((size_t)tap * 8 + ch) * 16 + n0g) * 2) * 32 + lane;
#pragma unroll
            for (int ks = 0; ks < 2; ks++) {
                uint4 B0 = wp[ks * 32];
                uint4 B1 = wp[ks * 32 + 64];
                uint4 B2 = wp[ks * 32 + 128];
                uint4 B3 = wp[ks * 32 + 192];
                const uint32_t kbyte = ks * 32;
#pragma unroll
                for (int mi = 0; mi < 4; mi++) {
                    uint32_t ah[4], al[4];
                    const uint32_t ao = pbase + (uint32_t)(mi * 16 * C1_ROWB) + kbyte;
                    ldsm_x4(ah, WHb + ao);
                    ldsm_x4(al, WLb + ao);
                    mma_bf16(acc[mi][0], ah, B0.x, B0.y);
                    mma_bf16(acc[mi][0], al, B0.x, B0.y);
                    mma_bf16(acc[mi][0], ah, B0.z, B0.w);
                    mma_bf16(acc[mi][1], ah, B1.x, B1.y);
                    mma_bf16(acc[mi][1], al, B1.x, B1.y);
                    mma_bf16(acc[mi][1], ah, B1.z, B1.w);
                    mma_bf16(acc[mi][2], ah, B2.x, B2.y);
                    mma_bf16(acc[mi][2], al, B2.x, B2.y);
                    mma_bf16(acc[mi][2], ah, B2.z, B2.w);
                    mma_bf16(acc[mi][3], ah, B3.x, B3.y);
                    mma_bf16(acc[mi][3], al, B3.x, B3.y);
                    mma_bf16(acc[mi][3], ah, B3.z, B3.w);
                }
            }
        }
        if (ch < 7) stage(ch + 1, buf ^ 1);
        __syncthreads();
    }

    // epilogue: leaky -> split -> h1 [pixlin][mid]
    const int dr = lane >> 2, dc = (lane & 3) * 2;
    const size_t slab = ((size_t)b * HWn + (size_t)y0 * Wn);
#pragma unroll
    for (int mi = 0; mi < 4; mi++)
#pragma unroll
        for (int j = 0; j < 4; j++) {
            int pix = m0w + mi * 16 + dr;
            int o = n0g * 8 + j * 8 + dc;
            float v0 = leaky(acc[mi][j][0]), v1 = leaky(acc[mi][j][1]);
            float v2 = leaky(acc[mi][j][2]), v3 = leaky(acc[mi][j][3]);
            size_t i1 = (slab + pix) * MIDn + o;
            size_t i2 = (slab + pix + 8) * MIDn + o;
            *(uint32_t*)(g_h1h + i1) = pack_hi(v0, v1);
            *(uint32_t*)(g_h1l + i1) = pack_lo(v0, v1);
            *(uint32_t*)(g_h1h + i2) = pack_hi(v2, v3);
            *(uint32_t*)(g_h1l + i2) = pack_lo(v2, v3);
        }
}

// ---------------- conv2: M=256 pix, N=128 o-half, K=128; + fused pool partials ----------------
#define G_AH 0
#define G_AL 36864
#define G_BH 73728
#define G_BL 92160
#define G_PR 110592
#define G_SMEM (G_PR + 512)

__global__ __launch_bounds__(512, 1) void conv2_tc() {
    extern __shared__ char sm[];
    const uint32_t sb = smem_u32(sm);
    __nv_bfloat16* sAh = (__nv_bfloat16*)(sm + G_AH);
    __nv_bfloat16* sAl = (__nv_bfloat16*)(sm + G_AL);
    __nv_bfloat16* sBh = (__nv_bfloat16*)(sm + G_BH);
    __nv_bfloat16* sBl = (__nv_bfloat16*)(sm + G_BL);
    float* pr = (float*)(sm + G_PR);
    const int tid = threadIdx.x, lane = tid & 31, wid = tid >> 5;
    const int yb = blockIdx.x, oh = blockIdx.y, b = blockIdx.z;
    const int m0w = (wid & 3) * 64, n0 = (wid >> 2) * 32;
    const uint32_t aoff = (uint32_t)((m0w + (lane & 15)) * ST + (lane >> 4) * 8) * 2;
    const uint32_t boff = (uint32_t)((n0 + (lane & 7) + ((lane >> 3) & 1) * 8) * ST + (lane >> 4) * 8) * 2;

    float acc[4][2][2][4];
#pragma unroll
    for (int mi = 0; mi < 4; mi++)
#pragma unroll
        for (int f = 0; f < 2; f++)
#pragma unroll
            for (int ns = 0; ns < 2; ns++)
#pragma unroll
                for (int q = 0; q < 4; q++) acc[mi][f][ns][q] = 0.f;

    const size_t slab = (size_t)b * HWn + (size_t)yb * 256;

    for (int kc = 0; kc < 128; kc += 64) {
        for (int i = tid; i < 2048; i += 512) {
            int row = i >> 3, q = i & 7;
            uint32_t so = row * ST + q * 8;
            *(uint4*)(sAh + so) = *(const uint4*)(g_h1h + (slab + row) * MIDn + kc + q * 8);
            *(uint4*)(sAl + so) = *(const uint4*)(g_h1l + (slab + row) * MIDn + kc + q * 8);
            if (i < 1024) {
                *(uint4*)(sBh + so) = *(const uint4*)(g_w2h + (size_t)(oh * 128 + row) * MIDn + kc + q * 8);
                *(uint4*)(sBl + so) = *(const uint4*)(g_w2l + (size_t)(oh * 128 + row) * MIDn + kc + q * 8);
            }
        }
        __syncthreads();
#pragma unroll
        for (int ks = 0; ks < 4; ks++) {
            const uint32_t kb = ks * 32;
            uint32_t bhm[8], blm[8];
            ldsm_x4(bhm,     sb + G_BH + boff + kb);
            ldsm_x4(bhm + 4, sb + G_BH + boff + 16 * ST * 2 + kb);
            ldsm_x4(blm,     sb + G_BL + boff + kb);
            ldsm_x4(blm + 4, sb + G_BL + boff + 16 * ST * 2 + kb);
#pragma unroll
            for (int mi = 0; mi < 4; mi++) {
                uint32_t ah[4], al[4];
                ldsm_x4(ah, sb + G_AH + aoff + mi * 16 * ST * 2 + kb);
                ldsm_x4(al, sb + G_AL + aoff + mi * 16 * ST * 2 + kb);
#pragma unroll
                for (int f = 0; f < 2; f++) {
                    mma_bf16(acc[mi][f][0], ah, bhm[4 * f],     bhm[4 * f + 2]);
                    mma_bf16(acc[mi][f][0], ah, blm[4 * f],     blm[4 * f + 2]);
                    mma_bf16(acc[mi][f][0], al, bhm[4 * f],     bhm[4 * f + 2]);
                    mma_bf16(acc[mi][f][1], ah, bhm[4 * f + 1], bhm[4 * f + 3]);
                    mma_bf16(acc[mi][f][1], ah, blm[4 * f + 1], blm[4 * f + 3]);
                    mma_bf16(acc[mi][f][1], al, bhm[4 * f + 1], bhm[4 * f + 3]);
                }
            }
        }
        __syncthreads();
    }

    if (tid < 128) pr[tid] = 0.f;
    __syncthreads();
    const int dr = lane >> 2, dc = (lane & 3) * 2;
#pragma unroll
    for (int f = 0; f < 2; f++)
#pragma unroll
        for (int ns = 0; ns < 2; ns++) {
            int cl = n0 + f * 16 + ns * 8 + dc;
            float s0 = 0.f, s1 = 0.f;
#pragma unroll
            for (int mi = 0; mi < 4; mi++) {
                int pix = m0w + mi * 16 + dr;
                float v0 = leaky(acc[mi][f][ns][0]), v1 = leaky(acc[mi][f][ns][1]);
                float v2 = leaky(acc[mi][f][ns][2]), v3 = leaky(acc[mi][f][ns][3]);
                size_t i1 = (slab + pix) * Cn + oh * 128 + cl;
                size_t i2 = (slab + pix + 8) * Cn + oh * 128 + cl;
                *(uint32_t*)(g_xch + i1) = pack_hi(v0, v1);
                *(uint32_t*)(g_xcl + i1) = pack_lo(v0, v1);
                *(uint32_t*)(g_xch + i2) = pack_hi(v2, v3);
                *(uint32_t*)(g_xcl + i2) = pack_lo(v2, v3);
                s0 += v0 + v2;
                s1 += v1 + v3;
            }
            atomicAdd(&pr[cl], s0);
            atomicAdd(&pr[cl + 1], s1);
        }
    __syncthreads();
    if (tid < 128)
        g_ppart[(((size_t)b * 64 + yb) * 2 + oh) * 128 + tid] = pr[tid];
}

// ---------------- pool2 ----------------
__global__ void pool2_kernel() {
    const int b = blockIdx.x, tid = threadIdx.x;
    const int oh = tid >> 7, cl = tid & 127;
    float s = 0.f;
    for (int yb = 0; yb < 64; yb++)
        s += g_ppart[(((size_t)b * 64 + yb) * 2 + oh) * 128 + cl];
    g_pooled[b * Cn + tid] = s * (1.0f / (float)HWn);
}

// ---------------- MLP + outer score + softmax ----------------
__global__ void mlp_score_kernel(const float* __restrict__ w1, const float* __restrict__ b1,
                                 const float* __restrict__ w2, const float* __restrict__ b2) {
    const int b = blockIdx.x, tid = threadIdx.x;
    __shared__ float sp[256], sh[64], sm_[256];
    sp[tid] = g_pooled[b * 256 + tid];
    __syncthreads();
    if (tid < 64) {
        float s = b1[tid];
        for (int c = 0; c < 256; c++) s += sp[c] * w1[tid * 256 + c];
        sh[tid] = leaky(s);
    }
    __syncthreads();
    {
        float s = b2[tid];
        for (int j = 0; j < 64; j++) s += sh[j] * w2[tid * 64 + j];
        sm_[tid] = s;
    }
    __syncthreads();
    const int lane = tid & 31, w = tid >> 5;
    for (int r = w; r < 256; r += 8) {
        float mr = sm_[r];
        float mx = -1e30f;
        for (int e = lane; e < 256; e += 32) mx = fmaxf(mx, mr * sm_[e]);
        for (int off = 16; off; off >>= 1) mx = fmaxf(mx, __shfl_xor_sync(~0u, mx, off));
        float sum = 0.f;
        for (int e = lane; e < 256; e += 32) sum += expf(mr * sm_[e] - mx);
        for (int off = 16; off; off >>= 1) sum += __shfl_xor_sync(~0u, sum, off);
        float inv = 1.0f / sum;
        for (int e = lane; e < 256; e += 32) {
            float s = expf(mr * sm_[e] - mx) * inv;
            __nv_bfloat16 h = __float2bfloat16(s);
            size_t off2 = ((size_t)b * 256 + r) * 256 + e;
            g_scoreH[off2] = h;
            g_scoreL[off2] = __float2bfloat16(s - __bfloat162float(h));
        }
    }
}

// ---------------- attn: M=256 pix, N=128 c-half, K=256; + residual + transpose ----------------
__global__ __launch_bounds__(512, 1) void attn_tc(float* __restrict__ out) {
    extern __shared__ char sm[];
    const uint32_t sb = smem_u32(sm);
    __nv_bfloat16* sAh = (__nv_bfloat16*)(sm + G_AH);
    __nv_bfloat16* sAl = (__nv_bfloat16*)(sm + G_AL);
    __nv_bfloat16* sBh = (__nv_bfloat16*)(sm + G_BH);
    __nv_bfloat16* sBl = (__nv_bfloat16*)(sm + G_BL);
    const int tid = threadIdx.x, lane = tid & 31, wid = tid >> 5;
    const int yb = blockIdx.x, mh = blockIdx.y, b = blockIdx.z;
    const int m0w = (wid & 3) * 64, n0 = (wid >> 2) * 32;
    const int yw = m0w >> 7;
    const uint32_t aoff = (uint32_t)((m0w + (lane & 15)) * ST + (lane >> 4) * 8) * 2;
    const uint32_t boff = (uint32_t)((n0 + (lane & 7) + ((lane >> 3) & 1) * 8) * ST + (lane >> 4) * 8) * 2;

    float acc[4][2][2][4];
#pragma unroll
    for (int mi = 0; mi < 4; mi++)
#pragma unroll
        for (int f = 0; f < 2; f++)
#pragma unroll
            for (int ns = 0; ns < 2; ns++)
#pragma unroll
                for (int q = 0; q < 4; q++) acc[mi][f][ns][q] = 0.f;

    const size_t slab = (size_t)b * HWn + (size_t)yb * 256;

    for (int kc = 0; kc < 256; kc += 64) {
        for (int i = tid; i < 2048; i += 512) {
            int row = i >> 3, q = i & 7;
            uint32_t so = row * ST + q * 8;
            *(uint4*)(sAh + so) = *(const uint4*)(g_xch + (slab + row) * Cn + kc + q * 8);
            *(uint4*)(sAl + so) = *(const uint4*)(g_xcl + (slab + row) * Cn + kc + q * 8);
            if (i < 1024) {
                *(uint4*)(sBh + so) = *(const uint4*)(g_scoreH + ((size_t)b * 256 + mh * 128 + row) * 256 + kc + q * 8);
                *(uint4*)(sBl + so) = *(const uint4*)(g_scoreL + ((size_t)b * 256 + mh * 128 + row) * 256 + kc + q * 8);
            }
        }
        __syncthreads();
#pragma unroll
        for (int ks = 0; ks < 4; ks++) {
            const uint32_t kb = ks * 32;
            uint32_t bhm[8], blm[8];
            ldsm_x4(bhm,     sb + G_BH + boff + kb);
            ldsm_x4(bhm + 4, sb + G_BH + boff + 16 * ST * 2 + kb);
            ldsm_x4(blm,     sb + G_BL + boff + kb);
            ldsm_x4(blm + 4, sb + G_BL + boff + 16 * ST * 2 + kb);
#pragma unroll
            for (int mi = 0; mi < 4; mi++) {
                uint32_t ah[4], al[4];
                ldsm_x4(ah, sb + G_AH + aoff + mi * 16 * ST * 2 + kb);
                ldsm_x4(al, sb + G_AL + aoff + mi * 16 * ST * 2 + kb);
#pragma unroll
                for (int f = 0; f < 2; f++) {
                    mma_bf16(acc[mi][f][0], ah, bhm[4 * f],     bhm[4 * f + 2]);
                    mma_bf16(acc[mi][f][0], ah, blm[4 * f],     blm[4 * f + 2]);
                    mma_bf16(acc[mi][f][0], al, bhm[4 * f],     bhm[4 * f + 2]);
                    mma_bf16(acc[mi][f][1], ah, bhm[4 * f + 1], bhm[4 * f + 3]);
                    mma_bf16(acc[mi][f][1], ah, blm[4 * f + 1], blm[4 * f + 3]);
                    mma_bf16(acc[mi][f][1], al, bhm[4 * f + 1], bhm[4 * f + 3]);
                }
            }
        }
        __syncthreads();
    }

    float* sT = (float*)sm;
    const int dr = lane >> 2, dc = (lane & 3) * 2;
    for (int yw2 = 0; yw2 < 2; yw2++) {
        if (yw == yw2) {
#pragma unroll
            for (int mi = 0; mi < 4; mi++)
#pragma unroll
                for (int f = 0; f < 2; f++)
#pragma unroll
                    for (int ns = 0; ns < 2; ns++) {
                        int pix = m0w + mi * 16 + dr;
                        int c = n0 + f * 16 + ns * 8 + dc;
                        size_t i1 = (slab + pix) * Cn + mh * 128 + c;
                        size_t i2 = (slab + pix + 8) * Cn + mh * 128 + c;
                        float r0 = __bfloat162float(g_xch[i1])     + __bfloat162float(g_xcl[i1]);
                        float r1 = __bfloat162float(g_xch[i1 + 1]) + __bfloat162float(g_xcl[i1 + 1]);
                        float r2 = __bfloat162float(g_xch[i2])     + __bfloat162float(g_xcl[i2]);
                        float r3 = __bfloat162float(g_xch[i2 + 1]) + __bfloat162float(g_xcl[i2 + 1]);
                        int p = pix & 127;
                        sT[c * 132 + p]           = acc[mi][f][ns][0] + r0;
                        sT[(c + 1) * 132 + p]     = acc[mi][f][ns][1] + r1;
                        sT[c * 132 + p + 8]       = acc[mi][f][ns][2] + r2;
                        sT[(c + 1) * 132 + p + 8] = acc[mi][f][ns][3] + r3;
                    }
        }
        __syncthreads();
        for (int i = tid; i < 16384; i += 512) {
            int c = i >> 7, p = i & 127;
            out[(((size_t)b * 256 + mh * 128 + c) * Hn + yb * 2 + yw2) * Wn + p] = sT[c * 132 + p];
        }
        __syncthreads();
    }
}

// ---------------- launcher ----------------
extern "C" void kernel_launch(void* const* d_in, const int* in_sizes, int n_in,
                              void* d_out, int out_size) {
    const float* x   = (const float*)d_in[0];
    const float* c1w = (const float*)d_in[1];
    const float* c2w = (const float*)d_in[2];
    const float* mw1 = (const float*)d_in[3];
    const float* mb1 = (const float*)d_in[4];
    const float* mw2 = (const float*)d_in[5];
    const float* mb2 = (const float*)d_in[6];
    float* out = (float*)d_out;

    cudaFuncSetAttribute(conv1_tc, cudaFuncAttributeMaxDynamicSharedMemorySize, C1_SMEM);
    cudaFuncSetAttribute(conv2_tc, cudaFuncAttributeMaxDynamicSharedMemorySize, G_SMEM);
    cudaFuncSetAttribute(attn_tc,  cudaFuncAttributeMaxDynamicSharedMemorySize, G_SMEM);

    prep_kernel<<<288, 256>>>(c1w, c2w);
    conv1_tc<<<dim3(64, Bn), 512, C1_SMEM>>>(x);
    conv2_tc<<<dim3(64, 2, Bn), 512, G_SMEM>>>();
    pool2_kernel<<<Bn, 256>>>();
    mlp_score_kernel<<<Bn, 256>>>(mw1, mb1, mw2, mb2);
    attn_tc<<<dim3(64, 2, Bn), 512, G_SMEM>>>(out);
}